// round 14
// baseline (speedup 1.0000x reference)
#include <cuda_runtime.h>
#include <cuda_fp16.h>
#include <math.h>
#include <stdint.h>

#define TOKENS 8192
#define HID    1024
#define FFN    4096
#define NUP    4864      // 4096 + 256 + 512 fused up-projection width

// ============================ scratch (device globals) ============================
__device__ __half g_xnh[TOKENS * HID];         // permuted row space
__device__ __half g_hh[TOKENS * FFN];          // permuted
__device__ float  g_mu[TOKENS], g_inv[TOKENS]; // permuted
__device__ __half g_ad0[TOKENS * HID], g_ad1[TOKENS * HID];   // permuted, fp16
__device__ __half g_t0h[TOKENS * 256];         // permuted
__device__ __half g_t1h[TOKENS * 512];         // permuted
__device__ __half g_wup[NUP * HID];
__device__ float  g_bup[NUP];
__device__ __half g_w2t[HID * FFN];            // (ln_h_g ∘ W2)^T fp16
__device__ __half g_a2t[HID * 256];
__device__ __half g_b2t[HID * 512];
__device__ float  g_c1[HID], g_c2[HID];
__device__ float  g_p1[64 * HID], g_p2[64 * HID];
__device__ float  g_ps[32 * TOKENS], g_pq[32 * TOKENS];   // rowstat partials per bn
__device__ int    g_perm[TOKENS];              // new(p) -> old(o)
__device__ int    g_pos[TOKENS];               // old(o) -> new(p)
__device__ int    g_counts[2];                 // c0, c0+c1

__device__ __forceinline__ float gelu_exact(float x) {
    return 0.5f * x * (1.0f + erff(x * 0.7071067811865475f));
}
__device__ __forceinline__ uint32_t smem_u32(const void* p) {
    uint32_t a;
    asm("{ .reg .u64 t; cvta.to.shared.u64 t, %1; cvt.u32.u64 %0, t; }" : "=r"(a) : "l"(p));
    return a;
}

#define CP_ASYNC16(s, g) \
    asm volatile("cp.async.cg.shared.global [%0], [%1], 16;" :: "r"(s), "l"(g))
#define CP_COMMIT() asm volatile("cp.async.commit_group;")
#define CP_WAIT1()  asm volatile("cp.async.wait_group 1;")
#define CP_WAIT0()  asm volatile("cp.async.wait_group 0;")

#define LDSM4(r0, r1, r2, r3, addr) \
    asm volatile("ldmatrix.sync.aligned.m8n8.x4.shared.b16 {%0,%1,%2,%3}, [%4];" \
                 : "=r"(r0), "=r"(r1), "=r"(r2), "=r"(r3) : "r"(addr))

#define MMA16816F16(d, a0, a1, a2, a3, b0, b1) \
    asm volatile("mma.sync.aligned.m16n8k16.row.col.f32.f16.f16.f32 " \
                 "{%0,%1,%2,%3}, {%4,%5,%6,%7}, {%8,%9}, {%0,%1,%2,%3};" \
                 : "+f"((d)[0]), "+f"((d)[1]), "+f"((d)[2]), "+f"((d)[3]) \
                 : "r"(a0), "r"(a1), "r"(a2), "r"(a3), "r"(b0), "r"(b1))

// ============================ weight prep ============================
__device__ __forceinline__ void do_transpose(
    const float* __restrict__ W, int K, int N, __half* __restrict__ T, int rowOff,
    const float* __restrict__ scale)
{
    __shared__ float s[32][33];
    const int n0 = blockIdx.x * 32, k0 = blockIdx.y * 32;
    if (n0 >= N || k0 >= K) return;
    const int tr = threadIdx.x >> 3;
    const int tc = (threadIdx.x & 7) * 4;
    const float4 v = *reinterpret_cast<const float4*>(W + (size_t)(k0 + tr) * N + n0 + tc);
    s[tr][tc + 0] = v.x; s[tr][tc + 1] = v.y; s[tr][tc + 2] = v.z; s[tr][tc + 3] = v.w;
    __syncthreads();
    const size_t off = (size_t)(rowOff + n0 + tr) * K + k0 + tc;
    #pragma unroll
    for (int q = 0; q < 2; ++q) {
        float x0 = s[tc + q * 2 + 0][tr];
        float x1 = s[tc + q * 2 + 1][tr];
        if (scale) {
            x0 *= scale[k0 + tc + q * 2 + 0];
            x1 *= scale[k0 + tc + q * 2 + 1];
        }
        *reinterpret_cast<__half2*>(T + off + q * 2) =
            __halves2half2(__float2half_rn(x0), __float2half_rn(x1));
    }
}

__global__ void __launch_bounds__(256) transpose_w1(
    const float* __restrict__ W1, __half* wup)
{
    do_transpose(W1, HID, FFN, wup, 0, nullptr);
}

__global__ void __launch_bounds__(256) transpose_w2(
    const float* __restrict__ W2, const float* __restrict__ lnhg, __half* w2t)
{
    do_transpose(W2, FFN, HID, w2t, 0, lnhg);
}

__global__ void __launch_bounds__(256) prep_weights(
    const float* __restrict__ aw1, const float* __restrict__ aw2,
    const float* __restrict__ bw1, const float* __restrict__ bw2,
    __half* wup, __half* a2t, __half* b2t,
    const float* __restrict__ b1, const float* __restrict__ ab1,
    const float* __restrict__ bb1, float* __restrict__ bup)
{
    switch (blockIdx.z) {
        case 0: do_transpose(aw1, HID, 256, wup, 4096, nullptr); break;
        case 1: do_transpose(aw2, 256, HID, a2t, 0, nullptr);    break;
        case 2: do_transpose(bw1, HID, 512, wup, 4352, nullptr); break;
        case 3: do_transpose(bw2, 512, HID, b2t, 0, nullptr);    break;
        default: {
            const int i = (blockIdx.y * 32 + blockIdx.x) * 256 + threadIdx.x;
            if (i < NUP) {
                float v;
                if (i < 4096) v = b1[i];
                else if (i < 4352) v = ab1[i - 4096];
                else v = bb1[i - 4352];
                bup[i] = v;
            }
            break;
        }
    }
}

// stable counting sort of 8192 idx values into perm/pos, 1 block x 256 threads
__global__ void __launch_bounds__(256) perm_kernel(
    const int* __restrict__ idx, int* __restrict__ perm,
    int* __restrict__ pos, int* __restrict__ counts)
{
    __shared__ int cnt[3][256];
    const int t = threadIdx.x;
    int l0 = 0, l1 = 0, l2 = 0;
    for (int i = 0; i < 32; ++i) {
        const int v = idx[t * 32 + i];
        l0 += (v == 0); l1 += (v == 1); l2 += (v == 2);
    }
    cnt[0][t] = l0; cnt[1][t] = l1; cnt[2][t] = l2;
    __syncthreads();
    for (int off = 1; off < 256; off <<= 1) {
        const int v0 = (t >= off) ? cnt[0][t - off] : 0;
        const int v1 = (t >= off) ? cnt[1][t - off] : 0;
        const int v2 = (t >= off) ? cnt[2][t - off] : 0;
        __syncthreads();
        cnt[0][t] += v0; cnt[1][t] += v1; cnt[2][t] += v2;
        __syncthreads();
    }
    const int tot0 = cnt[0][255], tot1 = cnt[1][255];
    int b0 = cnt[0][t] - l0;
    int b1 = tot0 + cnt[1][t] - l1;
    int b2 = tot0 + tot1 + cnt[2][t] - l2;
    for (int i = 0; i < 32; ++i) {
        const int o = t * 32 + i;
        const int v = idx[o];
        const int p = (v == 0) ? b0++ : ((v == 1) ? b1++ : b2++);
        perm[p] = o;
        pos[o]  = p;
    }
    if (t == 0) { counts[0] = tot0; counts[1] = tot0 + tot1; }
}

// c1[n] = sum_f g[f]*W2[f,n];  c2[n] = sum_f b[f]*W2[f,n] + b2[n]
__global__ void __launch_bounds__(128) colsum_partial(
    const float* __restrict__ W2, const float* __restrict__ g,
    const float* __restrict__ b, float* __restrict__ p1, float* __restrict__ p2)
{
    const int n = blockIdx.x * 128 + threadIdx.x;
    const int f0 = blockIdx.y * 64;
    float s1 = 0.0f, s2 = 0.0f;
    #pragma unroll 8
    for (int f = f0; f < f0 + 64; ++f) {
        const float w = W2[(size_t)f * HID + n];
        s1 += g[f] * w;
        s2 += b[f] * w;
    }
    p1[blockIdx.y * HID + n] = s1;
    p2[blockIdx.y * HID + n] = s2;
}

__global__ void __launch_bounds__(256) colsum_reduce(
    const float* __restrict__ p1, const float* __restrict__ p2,
    const float* __restrict__ b2, float* __restrict__ c1, float* __restrict__ c2)
{
    const int n = blockIdx.x * 256 + threadIdx.x;
    float s1 = 0.0f, s2 = 0.0f;
    #pragma unroll
    for (int q = 0; q < 64; ++q) { s1 += p1[q * HID + n]; s2 += p2[q * HID + n]; }
    c1[n] = s1;
    c2[n] = s2 + b2[n];
}

// ============================ LayerNorm: warp-per-row ============================
__global__ void __launch_bounds__(256) ln1024_warp(
    const float* __restrict__ in, const float* __restrict__ gw,
    const float* __restrict__ bw, const int* __restrict__ pos,
    __half* __restrict__ oh)
{
    const int lane = threadIdx.x & 31;
    const int row  = blockIdx.x * 8 + (threadIdx.x >> 5);
    const float4* inr = reinterpret_cast<const float4*>(in) + (size_t)row * 256;

    float4 v[8];
    float s = 0.0f, ss = 0.0f;
    #pragma unroll
    for (int i = 0; i < 8; ++i) {
        v[i] = inr[lane + i * 32];
        s  += v[i].x + v[i].y + v[i].z + v[i].w;
        ss += v[i].x * v[i].x + v[i].y * v[i].y + v[i].z * v[i].z + v[i].w * v[i].w;
    }
    #pragma unroll
    for (int off = 16; off > 0; off >>= 1) {
        s  += __shfl_xor_sync(0xffffffffu, s, off);
        ss += __shfl_xor_sync(0xffffffffu, ss, off);
    }
    const float mu  = s * (1.0f / HID);
    const float var = ss * (1.0f / HID) - mu * mu;
    const float inv = rsqrtf(var + 1e-5f);

    const float4* g4 = reinterpret_cast<const float4*>(gw);
    const float4* b4 = reinterpret_cast<const float4*>(bw);
    __half2* ohr = reinterpret_cast<__half2*>(oh) + (size_t)pos[row] * 512;
    #pragma unroll
    for (int i = 0; i < 8; ++i) {
        const int c = lane + i * 32;
        const float4 gv = g4[c], bv = b4[c], x = v[i];
        float4 o;
        o.x = (x.x - mu) * inv * gv.x + bv.x;
        o.y = (x.y - mu) * inv * gv.y + bv.y;
        o.z = (x.z - mu) * inv * gv.z + bv.z;
        o.w = (x.w - mu) * inv * gv.w + bv.w;
        ohr[c * 2 + 0] = __halves2half2(__float2half_rn(o.x), __float2half_rn(o.y));
        ohr[c * 2 + 1] = __halves2half2(__float2half_rn(o.z), __float2half_rn(o.w));
    }
}

// rowstat final reduce over 32 per-bn partials
__global__ void __launch_bounds__(256) rowstat_reduce(
    const float* __restrict__ ps, const float* __restrict__ pq,
    float* __restrict__ mu, float* __restrict__ inv)
{
    const int r = blockIdx.x * 256 + threadIdx.x;
    float s = 0.0f, q = 0.0f;
    #pragma unroll
    for (int bn = 0; bn < 32; ++bn) {
        s += ps[bn * TOKENS + r];
        q += pq[bn * TOKENS + r];
    }
    const float m = s * (1.0f / FFN);
    mu[r]  = m;
    inv[r] = rsqrtf(q * (1.0f / FFN) - m * m + 1e-5f);
}

// ============================ fp16 mma.sync GEMM mainloop ============================
// CTA 128x128, BK=64, 8 warps (2x4 of 64x32), 3-stage cp.async, occ 2.
// A-fragment LDSMs software-pipelined one j-step ahead (double buffered).
#define GSTAGES 3
#define GSTAGE_BYTES 32768
#define GEMM_SMEM (GSTAGES * GSTAGE_BYTES)

__device__ __forceinline__ void issue_tile(
    uint32_t dstA, uint32_t dstB,
    const __half* gA, const __half* gB, size_t gStride)
{
    #pragma unroll
    for (int p = 0; p < 4; ++p)
        CP_ASYNC16(dstA + p * 4096, gA + p * gStride);
    #pragma unroll
    for (int p = 0; p < 4; ++p)
        CP_ASYNC16(dstB + p * 4096, gB + p * gStride);
    CP_COMMIT();
}

__device__ __forceinline__ void gemm_mainloop(
    const __half* __restrict__ A, const __half* __restrict__ B,
    int K, int bm, int bn, float (&acc)[4][4][4])
{
    extern __shared__ char smem[];
    const uint32_t sbase = smem_u32(smem);
    const int tid = threadIdx.x, lane = tid & 31, wid = tid >> 5;
    const int warp_m = wid & 1, warp_n = wid >> 1;

    const int lrow = tid >> 3;
    const int lch  = tid & 7;
    const uint32_t sOffA = (uint32_t)lrow * 128 + ((lch ^ (lrow & 7)) << 4);
    const uint32_t sOffB = sOffA + 16384;
    const __half* gA = A + (size_t)(bm * 128 + lrow) * K + lch * 8;
    const __half* gB = B + (size_t)(bn * 128 + lrow) * K + lch * 8;
    const size_t gStride = (size_t)32 * K;

    // swizzle term is identical for every fragment row (rows differ by multiples of 8)
    const uint32_t sw = (uint32_t)(lane & 7) << 4;
    const uint32_t hiA = (lane & 16);
    const uint32_t hiB = ((lane & 8) << 1);
    uint32_t aAddr[4], bAddr[2];
    #pragma unroll
    for (int mt = 0; mt < 4; ++mt)
        aAddr[mt] = sbase + (warp_m * 64 + mt * 16 + (lane & 15)) * 128;
    #pragma unroll
    for (int ng = 0; ng < 2; ++ng)
        bAddr[ng] = sbase + 16384 +
                    (warp_n * 32 + ng * 16 + (lane & 7) + ((lane & 16) >> 1)) * 128;

    #pragma unroll
    for (int i = 0; i < 4; ++i)
        #pragma unroll
        for (int j = 0; j < 4; ++j)
            #pragma unroll
            for (int q = 0; q < 4; ++q) acc[i][j][q] = 0.0f;

    const int ntile = K >> 6;

    issue_tile(sbase + sOffA, sbase + sOffB, gA, gB, gStride);
    gA += 64; gB += 64;
    issue_tile(sbase + GSTAGE_BYTES + sOffA, sbase + GSTAGE_BYTES + sOffB, gA, gB, gStride);
    gA += 64; gB += 64;

    uint32_t wOff = 2 * GSTAGE_BYTES, rOff = 0;

    for (int t = 0; t < ntile; ++t) {
        if (t == ntile - 1) { CP_WAIT0(); } else { CP_WAIT1(); }
        __syncthreads();
        if (t + 2 < ntile) {
            issue_tile(sbase + wOff + sOffA, sbase + wOff + sOffB, gA, gB, gStride);
            gA += 64; gB += 64;
            wOff = (wOff == 2 * GSTAGE_BYTES) ? 0u : wOff + GSTAGE_BYTES;
        }

        uint32_t afr[2][4][4];
        // prefetch A fragments for j = 0
        #pragma unroll
        for (int mt = 0; mt < 4; ++mt)
            LDSM4(afr[0][mt][0], afr[0][mt][1], afr[0][mt][2], afr[0][mt][3],
                  aAddr[mt] + rOff + (hiA ^ sw));

        #pragma unroll
        for (int j = 0; j < 4; ++j) {
            const int cur = j & 1, nxt = cur ^ 1;
            uint32_t b[2][4];
            #pragma unroll
            for (int ng = 0; ng < 2; ++ng)
                LDSM4(b[ng][0], b[ng][1], b[ng][2], b[ng][3],
                      bAddr[ng] + rOff + (((uint32_t)(j * 32) + hiB) ^ sw));
            if (j < 3) {
                #pragma unroll
                for (int mt = 0; mt < 4; ++mt)
                    LDSM4(afr[nxt][mt][0], afr[nxt][mt][1], afr[nxt][mt][2], afr[nxt][mt][3],
                          aAddr[mt] + rOff + (((uint32_t)((j + 1) * 32) + hiA) ^ sw));
            }
            #pragma unroll
            for (int mt = 0; mt < 4; ++mt)
                #pragma unroll
                for (int nt = 0; nt < 4; ++nt) {
                    const int ng = nt >> 1;
                    if (nt & 1) MMA16816F16(acc[mt][nt],
                                            afr[cur][mt][0], afr[cur][mt][1],
                                            afr[cur][mt][2], afr[cur][mt][3],
                                            b[ng][2], b[ng][3]);
                    else        MMA16816F16(acc[mt][nt],
                                            afr[cur][mt][0], afr[cur][mt][1],
                                            afr[cur][mt][2], afr[cur][mt][3],
                                            b[ng][0], b[ng][1]);
                }
        }
        rOff = (rOff == 2 * GSTAGE_BYTES) ? 0u : rOff + GSTAGE_BYTES;
    }
}

// ---- up-projection, h columns only (bn 0..31), + fused rowstat partials ----
__global__ void __launch_bounds__(256, 2) gemm_up_h(
    const __half* __restrict__ A, const __half* __restrict__ B,
    const float* __restrict__ bias, __half* __restrict__ Hh,
    float* __restrict__ ps, float* __restrict__ pq)
{
    extern __shared__ char smem[];
    float acc[4][4][4];
    const int bm = blockIdx.y, bn = blockIdx.x;
    gemm_mainloop(A, B, HID, bm, bn, acc);

    const int lane = threadIdx.x & 31, wid = threadIdx.x >> 5;
    const int warp_m = wid & 1, warp_n = wid >> 1;
    const int row0 = bm * 128 + warp_m * 64 + (lane >> 2);
    const int cw   = warp_n * 32 + (lane & 3) * 2;

    float rs[8], rq[8];
    #pragma unroll
    for (int i = 0; i < 8; ++i) { rs[i] = 0.0f; rq[i] = 0.0f; }

    #pragma unroll
    for (int mt = 0; mt < 4; ++mt) {
        #pragma unroll
        for (int nt = 0; nt < 4; ++nt) {
            const int gc = bn * 128 + cw + nt * 8;
            const float bz0 = bias[gc], bz1 = bias[gc + 1];
            float v[4];
            v[0] = gelu_exact(acc[mt][nt][0] + bz0);
            v[1] = gelu_exact(acc[mt][nt][1] + bz1);
            v[2] = gelu_exact(acc[mt][nt][2] + bz0);
            v[3] = gelu_exact(acc[mt][nt][3] + bz1);
            const __half2 hv0 = __halves2half2(__float2half_rn(v[0]), __float2half_rn(v[1]));
            const __half2 hv1 = __halves2half2(__float2half_rn(v[2]), __float2half_rn(v[3]));
            const size_t r0 = (size_t)(row0 + mt * 16);
            const size_t r1 = r0 + 8;
            *reinterpret_cast<__half2*>(Hh + r0 * FFN + gc) = hv0;
            *reinterpret_cast<__half2*>(Hh + r1 * FFN + gc) = hv1;
            const float2 f0 = __half22float2(hv0);
            const float2 f1 = __half22float2(hv1);
            rs[mt * 2 + 0] += f0.x + f0.y;
            rq[mt * 2 + 0] += f0.x * f0.x + f0.y * f0.y;
            rs[mt * 2 + 1] += f1.x + f1.y;
            rq[mt * 2 + 1] += f1.x * f1.x + f1.y * f1.y;
        }
    }

    #pragma unroll
    for (int i = 0; i < 8; ++i) {
        rs[i] += __shfl_xor_sync(0xffffffffu, rs[i], 1);
        rs[i] += __shfl_xor_sync(0xffffffffu, rs[i], 2);
        rq[i] += __shfl_xor_sync(0xffffffffu, rq[i], 1);
        rq[i] += __shfl_xor_sync(0xffffffffu, rq[i], 2);
    }
    __syncthreads();
    float* sred  = reinterpret_cast<float*>(smem);
    float* sred2 = sred + 512;
    if ((lane & 3) == 0) {
        #pragma unroll
        for (int i = 0; i < 8; ++i) {
            const int lr = warp_m * 64 + (i >> 1) * 16 + (i & 1) * 8 + (lane >> 2);
            sred [lr * 4 + warp_n] = rs[i];
            sred2[lr * 4 + warp_n] = rq[i];
        }
    }
    __syncthreads();
    if (threadIdx.x < 128) {
        const int lr = threadIdx.x;
        const float s = sred [lr * 4] + sred [lr * 4 + 1] + sred [lr * 4 + 2] + sred [lr * 4 + 3];
        const float q = sred2[lr * 4] + sred2[lr * 4 + 1] + sred2[lr * 4 + 2] + sred2[lr * 4 + 3];
        ps[bn * TOKENS + bm * 128 + lr] = s;
        pq[bn * TOKENS + bm * 128 + lr] = q;
    }
}

// ---- up-projection, adapter columns (logical bn 32..37), routed early-exit ----
__global__ void __launch_bounds__(256, 2) gemm_up_adapt(
    const __half* __restrict__ A, const __half* __restrict__ B,
    const float* __restrict__ bias, const int* __restrict__ counts,
    __half* __restrict__ T0, __half* __restrict__ T1)
{
    const int bm = blockIdx.y;
    const int bn = blockIdx.x + 32;            // 32..37
    if (bn < 34) {
        if (bm * 128 >= counts[0]) return;
    } else {
        if (bm * 128 >= counts[1] || bm * 128 + 128 <= counts[0]) return;
    }
    float acc[4][4][4];
    gemm_mainloop(A, B, HID, bm, bn, acc);

    __half* outH; int No; int colL;
    if (bn < 34) { outH = T0; No = 256; colL = (bn - 32) * 128; }
    else         { outH = T1; No = 512; colL = (bn - 34) * 128; }

    const int lane = threadIdx.x & 31, wid = threadIdx.x >> 5;
    const int warp_m = wid & 1, warp_n = wid >> 1;
    const int row0 = bm * 128 + warp_m * 64 + (lane >> 2);
    const int cw   = warp_n * 32 + (lane & 3) * 2;

    #pragma unroll
    for (int mt = 0; mt < 4; ++mt) {
        #pragma unroll
        for (int nt = 0; nt < 4; ++nt) {
            const int cc = cw + nt * 8;
            const float bz0 = bias[bn * 128 + cc];
            const float bz1 = bias[bn * 128 + cc + 1];
            float v[4];
            v[0] = gelu_exact(acc[mt][nt][0] + bz0);
            v[1] = gelu_exact(acc[mt][nt][1] + bz1);
            v[2] = gelu_exact(acc[mt][nt][2] + bz0);
            v[3] = gelu_exact(acc[mt][nt][3] + bz1);
            const int gc = colL + cc;
            const size_t r0 = (size_t)(row0 + mt * 16);
            const size_t r1 = r0 + 8;
            *reinterpret_cast<__half2*>(outH + r0 * No + gc) =
                __halves2half2(__float2half_rn(v[0]), __float2half_rn(v[1]));
            *reinterpret_cast<__half2*>(outH + r1 * No + gc) =
                __halves2half2(__float2half_rn(v[2]), __float2half_rn(v[3]));
        }
    }
}

// ---- adapter-down with routed early-exit, fp16 output ----
__global__ void __launch_bounds__(256, 2) gemm_down(
    const __half* __restrict__ A0, const __half* __restrict__ B0,
    const float* __restrict__ bias0, __half* __restrict__ C0,
    const __half* __restrict__ A1, const __half* __restrict__ B1,
    const float* __restrict__ bias1, __half* __restrict__ C1,
    const int* __restrict__ counts)
{
    const int bm = blockIdx.y, bn = blockIdx.x;
    const __half* A; const __half* B; const float* bias; __half* C; int K;
    if (blockIdx.z == 0) {
        if (bm * 128 >= counts[0]) return;
        A = A0; B = B0; bias = bias0; C = C0; K = 256;
    } else {
        if (bm * 128 >= counts[1] || bm * 128 + 128 <= counts[0]) return;
        A = A1; B = B1; bias = bias1; C = C1; K = 512;
    }
    float acc[4][4][4];
    gemm_mainloop(A, B, K, bm, bn, acc);

    const int lane = threadIdx.x & 31, wid = threadIdx.x >> 5;
    const int warp_m = wid & 1, warp_n = wid >> 1;
    const int row0 = bm * 128 + warp_m * 64 + (lane >> 2);
    const int cw   = warp_n * 32 + (lane & 3) * 2;

    #pragma unroll
    for (int mt = 0; mt < 4; ++mt) {
        #pragma unroll
        for (int nt = 0; nt < 4; ++nt) {
            const int cc = cw + nt * 8;
            const int gc = bn * 128 + cc;
            const float bz0 = bias[gc], bz1 = bias[gc + 1];
            const size_t r0 = (size_t)(row0 + mt * 16);
            const size_t r1 = r0 + 8;
            *reinterpret_cast<__half2*>(C + r0 * HID + gc) =
                __halves2half2(__float2half_rn(acc[mt][nt][0] + bz0),
                               __float2half_rn(acc[mt][nt][1] + bz1));
            *reinterpret_cast<__half2*>(C + r1 * HID + gc) =
                __halves2half2(__float2half_rn(acc[mt][nt][2] + bz0),
                               __float2half_rn(acc[mt][nt][3] + bz1));
        }
    }
}

// ---- final GEMM: LN-correction + routed combine + un-permute on store ----
__global__ void __launch_bounds__(256, 2) gemm_final(
    const __half* __restrict__ A, const __half* __restrict__ B,
    const float* __restrict__ c1, const float* __restrict__ c2,
    const float* __restrict__ mu, const float* __restrict__ inv,
    const float* __restrict__ wm, const int* __restrict__ perm,
    const int* __restrict__ counts,
    const __half* __restrict__ ad0, const __half* __restrict__ ad1,
    const __half* __restrict__ xnh, float* __restrict__ out)
{
    float acc[4][4][4];
    const int bm = blockIdx.y, bn = blockIdx.x;
    gemm_mainloop(A, B, FFN, bm, bn, acc);

    const int lane = threadIdx.x & 31, wid = threadIdx.x >> 5;
    const int warp_m = wid & 1, warp_n = wid >> 1;
    const int row0 = bm * 128 + warp_m * 64 + (lane >> 2);
    const int cw   = warp_n * 32 + (lane & 3) * 2;
    const int c0 = counts[0], c01 = counts[1];

    #pragma unroll
    for (int mt = 0; mt < 4; ++mt) {
        #pragma unroll
        for (int rr = 0; rr < 2; ++rr) {
            const int p = row0 + mt * 16 + rr * 8;      // permuted row
            const int o = perm[p];                       // original row
            const float muv = mu[p], invv = inv[p];
            const float w = wm[o], w1 = 1.0f - w;
            const __half* src = (p < c0) ? ad0 : ((p < c01) ? ad1 : xnh);
            #pragma unroll
            for (int nt = 0; nt < 4; ++nt) {
                const int gc = bn * 128 + cw + nt * 8;
                const float v0 = invv * (acc[mt][nt][rr * 2 + 0] - muv * c1[gc])     + c2[gc];
                const float v1 = invv * (acc[mt][nt][rr * 2 + 1] - muv * c1[gc + 1]) + c2[gc + 1];
                const float2 f = __half22float2(
                    *reinterpret_cast<const __half2*>(src + (size_t)p * HID + gc));
                *reinterpret_cast<float2*>(out + (size_t)o * HID + gc) =
                    make_float2(v0 * w + f.x * w1, v1 * w + f.y * w1);
            }
        }
    }
}

// ============================ launch ============================
extern "C" void kernel_launch(void* const* d_in, const int* in_sizes, int n_in,
                              void* d_out, int out_size)
{
    const float* x        = (const float*)d_in[0];
    const float* wm       = (const float*)d_in[1];
    const int*   widx     = (const int*)  d_in[2];
    const float* ln_in_g  = (const float*)d_in[3];
    const float* ln_in_b  = (const float*)d_in[4];
    const float* W1       = (const float*)d_in[5];
    const float* b1       = (const float*)d_in[6];
    const float* ln_h_g   = (const float*)d_in[7];
    const float* ln_h_b   = (const float*)d_in[8];
    const float* W2       = (const float*)d_in[9];
    const float* b2       = (const float*)d_in[10];
    const float* a256_w1  = (const float*)d_in[11];
    const float* a256_b1  = (const float*)d_in[12];
    const float* a256_w2  = (const float*)d_in[13];
    const float* a256_b2  = (const float*)d_in[14];
    const float* a512_w1  = (const float*)d_in[15];
    const float* a512_b1  = (const float*)d_in[16];
    const float* a512_w2  = (const float*)d_in[17];
    const float* a512_b2  = (const float*)d_in[18];
    float* out = (float*)d_out;

    cudaFuncSetAttribute(gemm_up_h,     cudaFuncAttributeMaxDynamicSharedMemorySize, GEMM_SMEM);
    cudaFuncSetAttribute(gemm_up_adapt, cudaFuncAttributeMaxDynamicSharedMemorySize, GEMM_SMEM);
    cudaFuncSetAttribute(gemm_down,     cudaFuncAttributeMaxDynamicSharedMemorySize, GEMM_SMEM);
    cudaFuncSetAttribute(gemm_final,    cudaFuncAttributeMaxDynamicSharedMemorySize, GEMM_SMEM);

    float *bup, *mu, *inv, *c1, *c2, *p1, *p2, *ps, *pq;
    __half *xnh, *hh, *t0h, *t1h, *wup, *w2t, *a2t, *b2t, *ad0, *ad1;
    int *perm, *pos, *counts;
    cudaGetSymbolAddress((void**)&ad0,   g_ad0);
    cudaGetSymbolAddress((void**)&ad1,   g_ad1);
    cudaGetSymbolAddress((void**)&bup,   g_bup);
    cudaGetSymbolAddress((void**)&mu,    g_mu);
    cudaGetSymbolAddress((void**)&inv,   g_inv);
    cudaGetSymbolAddress((void**)&c1,    g_c1);
    cudaGetSymbolAddress((void**)&c2,    g_c2);
    cudaGetSymbolAddress((void**)&p1,    g_p1);
    cudaGetSymbolAddress((void**)&p2,    g_p2);
    cudaGetSymbolAddress((void**)&ps,    g_ps);
    cudaGetSymbolAddress((void**)&pq,    g_pq);
    cudaGetSymbolAddress((void**)&xnh,   g_xnh);
    cudaGetSymbolAddress((void**)&hh,    g_hh);
    cudaGetSymbolAddress((void**)&t0h,   g_t0h);
    cudaGetSymbolAddress((void**)&t1h,   g_t1h);
    cudaGetSymbolAddress((void**)&wup,   g_wup);
    cudaGetSymbolAddress((void**)&w2t,   g_w2t);
    cudaGetSymbolAddress((void**)&a2t,   g_a2t);
    cudaGetSymbolAddress((void**)&b2t,   g_b2t);
    cudaGetSymbolAddress((void**)&perm,  g_perm);
    cudaGetSymbolAddress((void**)&pos,   g_pos);
    cudaGetSymbolAddress((void**)&counts, g_counts);

    static cudaStream_t s2 = nullptr;
    static cudaEvent_t evFork = nullptr, evW = nullptr, evLn = nullptr, evSide = nullptr;
    if (s2 == nullptr) {
        cudaStreamCreateWithFlags(&s2, cudaStreamNonBlocking);
        cudaEventCreateWithFlags(&evFork, cudaEventDisableTiming);
        cudaEventCreateWithFlags(&evW,    cudaEventDisableTiming);
        cudaEventCreateWithFlags(&evLn,   cudaEventDisableTiming);
        cudaEventCreateWithFlags(&evSide, cudaEventDisableTiming);
    }

    // ---- fork side stream: all weight prep ----
    cudaEventRecord(evFork, 0);
    cudaStreamWaitEvent(s2, evFork, 0);
    transpose_w1<<<dim3(FFN / 32, HID / 32), 256, 0, s2>>>(W1, wup);
    prep_weights<<<dim3(32, 32, 5), 256, 0, s2>>>(a256_w1, a256_w2, a512_w1, a512_w2,
                                                  wup, a2t, b2t,
                                                  b1, a256_b1, a512_b1, bup);
    cudaEventRecord(evW, s2);      // wup/bup (and a2t/b2t in-stream) ready
    transpose_w2<<<dim3(HID / 32, FFN / 32), 256, 0, s2>>>(W2, ln_h_g, w2t);
    colsum_partial<<<dim3(HID / 128, 64), 128, 0, s2>>>(W2, ln_h_g, ln_h_b, p1, p2);
    colsum_reduce<<<HID / 256, 256, 0, s2>>>(p1, p2, b2, c1, c2);

    // ---- main chain: perm -> LN ----
    perm_kernel<<<1, 256>>>(widx, perm, pos, counts);
    ln1024_warp<<<TOKENS / 8, 256>>>(x, ln_in_g, ln_in_b, pos, xnh);
    cudaEventRecord(evLn, 0);

    // ---- side stream: adapter up + adapter down (overlaps with up_h) ----
    cudaStreamWaitEvent(s2, evLn, 0);
    gemm_up_adapt<<<dim3(6, TOKENS / 128), 256, GEMM_SMEM, s2>>>(
        xnh, wup, bup, counts, t0h, t1h);
    gemm_down<<<dim3(HID / 128, TOKENS / 128, 2), 256, GEMM_SMEM, s2>>>(
        t0h, a2t, a256_b2, ad0, t1h, b2t, a512_b2, ad1, counts);
    cudaEventRecord(evSide, s2);

    // ---- main chain: big up-projection (fused rowstat partials), reduce ----
    cudaStreamWaitEvent(0, evW, 0);
    gemm_up_h<<<dim3(FFN / 128, TOKENS / 128), 256, GEMM_SMEM>>>(xnh, wup, bup, hh, ps, pq);
    rowstat_reduce<<<TOKENS / 256, 256>>>(ps, pq, mu, inv);

    // ---- join, final ----
    cudaStreamWaitEvent(0, evSide, 0);
    gemm_final<<<dim3(HID / 128, TOKENS / 128), 256, GEMM_SMEM>>>(
        hh, w2t, c1, c2, mu, inv, wm, perm, counts, ad0, ad1, xnh, out);
}

// round 15
// speedup vs baseline: 1.0220x; 1.0220x over previous
#include <cuda_runtime.h>
#include <cuda_fp16.h>
#include <math.h>
#include <stdint.h>

#define TOKENS 8192
#define HID    1024
#define FFN    4096
#define NUP    4864      // 4096 + 256 + 512 fused up-projection width

// ============================ scratch (device globals) ============================
__device__ __half g_xnh[TOKENS * HID];         // permuted row space
__device__ __half g_hh[TOKENS * FFN];          // permuted
__device__ float  g_mu[TOKENS], g_inv[TOKENS]; // permuted
__device__ __half g_ad0[TOKENS * HID], g_ad1[TOKENS * HID];   // permuted, fp16
__device__ __half g_t0h[TOKENS * 256];         // permuted
__device__ __half g_t1h[TOKENS * 512];         // permuted
__device__ __half g_wup[NUP * HID];
__device__ float  g_bup[NUP];
__device__ __half g_w2t[HID * FFN];            // (ln_h_g ∘ W2)^T fp16
__device__ __half g_a2t[HID * 256];
__device__ __half g_b2t[HID * 512];
__device__ float  g_c1[HID], g_c2[HID];
__device__ float  g_p1[64 * HID], g_p2[64 * HID];
__device__ float  g_ps[32 * TOKENS], g_pq[32 * TOKENS];   // rowstat partials per bn
__device__ int    g_perm[TOKENS];              // new(p) -> old(o)
__device__ int    g_pos[TOKENS];               // old(o) -> new(p)
__device__ int    g_counts[2];                 // c0, c0+c1

__device__ __forceinline__ float gelu_exact(float x) {
    return 0.5f * x * (1.0f + erff(x * 0.7071067811865475f));
}
__device__ __forceinline__ uint32_t smem_u32(const void* p) {
    uint32_t a;
    asm("{ .reg .u64 t; cvta.to.shared.u64 t, %1; cvt.u32.u64 %0, t; }" : "=r"(a) : "l"(p));
    return a;
}

#define CP_ASYNC16(s, g) \
    asm volatile("cp.async.cg.shared.global [%0], [%1], 16;" :: "r"(s), "l"(g))
#define CP_COMMIT() asm volatile("cp.async.commit_group;")
#define CP_WAIT1()  asm volatile("cp.async.wait_group 1;")
#define CP_WAIT0()  asm volatile("cp.async.wait_group 0;")

#define LDSM4(r0, r1, r2, r3, addr) \
    asm volatile("ldmatrix.sync.aligned.m8n8.x4.shared.b16 {%0,%1,%2,%3}, [%4];" \
                 : "=r"(r0), "=r"(r1), "=r"(r2), "=r"(r3) : "r"(addr))

#define MMA16816F16(d, a0, a1, a2, a3, b0, b1) \
    asm volatile("mma.sync.aligned.m16n8k16.row.col.f32.f16.f16.f32 " \
                 "{%0,%1,%2,%3}, {%4,%5,%6,%7}, {%8,%9}, {%0,%1,%2,%3};" \
                 : "+f"((d)[0]), "+f"((d)[1]), "+f"((d)[2]), "+f"((d)[3]) \
                 : "r"(a0), "r"(a1), "r"(a2), "r"(a3), "r"(b0), "r"(b1))

// ============================ weight prep ============================
__device__ __forceinline__ void do_transpose(
    const float* __restrict__ W, int K, int N, __half* __restrict__ T, int rowOff,
    const float* __restrict__ scale)
{
    __shared__ float s[32][33];
    const int n0 = blockIdx.x * 32, k0 = blockIdx.y * 32;
    if (n0 >= N || k0 >= K) return;
    const int tr = threadIdx.x >> 3;
    const int tc = (threadIdx.x & 7) * 4;
    const float4 v = *reinterpret_cast<const float4*>(W + (size_t)(k0 + tr) * N + n0 + tc);
    s[tr][tc + 0] = v.x; s[tr][tc + 1] = v.y; s[tr][tc + 2] = v.z; s[tr][tc + 3] = v.w;
    __syncthreads();
    const size_t off = (size_t)(rowOff + n0 + tr) * K + k0 + tc;
    #pragma unroll
    for (int q = 0; q < 2; ++q) {
        float x0 = s[tc + q * 2 + 0][tr];
        float x1 = s[tc + q * 2 + 1][tr];
        if (scale) {
            x0 *= scale[k0 + tc + q * 2 + 0];
            x1 *= scale[k0 + tc + q * 2 + 1];
        }
        *reinterpret_cast<__half2*>(T + off + q * 2) =
            __halves2half2(__float2half_rn(x0), __float2half_rn(x1));
    }
}

__global__ void __launch_bounds__(256) transpose_w1(
    const float* __restrict__ W1, __half* wup)
{
    do_transpose(W1, HID, FFN, wup, 0, nullptr);
}

__global__ void __launch_bounds__(256) transpose_w2(
    const float* __restrict__ W2, const float* __restrict__ lnhg, __half* w2t)
{
    do_transpose(W2, FFN, HID, w2t, 0, lnhg);
}

__global__ void __launch_bounds__(256) prep_weights(
    const float* __restrict__ aw1, const float* __restrict__ aw2,
    const float* __restrict__ bw1, const float* __restrict__ bw2,
    __half* wup, __half* a2t, __half* b2t,
    const float* __restrict__ b1, const float* __restrict__ ab1,
    const float* __restrict__ bb1, float* __restrict__ bup)
{
    switch (blockIdx.z) {
        case 0: do_transpose(aw1, HID, 256, wup, 4096, nullptr); break;
        case 1: do_transpose(aw2, 256, HID, a2t, 0, nullptr);    break;
        case 2: do_transpose(bw1, HID, 512, wup, 4352, nullptr); break;
        case 3: do_transpose(bw2, 512, HID, b2t, 0, nullptr);    break;
        default: {
            const int i = (blockIdx.y * 32 + blockIdx.x) * 256 + threadIdx.x;
            if (i < NUP) {
                float v;
                if (i < 4096) v = b1[i];
                else if (i < 4352) v = ab1[i - 4096];
                else v = bb1[i - 4352];
                bup[i] = v;
            }
            break;
        }
    }
}

// stable counting sort of 8192 idx values into perm/pos, 1 block x 256 threads
__global__ void __launch_bounds__(256) perm_kernel(
    const int* __restrict__ idx, int* __restrict__ perm,
    int* __restrict__ pos, int* __restrict__ counts)
{
    __shared__ int cnt[3][256];
    const int t = threadIdx.x;
    int l0 = 0, l1 = 0, l2 = 0;
    for (int i = 0; i < 32; ++i) {
        const int v = idx[t * 32 + i];
        l0 += (v == 0); l1 += (v == 1); l2 += (v == 2);
    }
    cnt[0][t] = l0; cnt[1][t] = l1; cnt[2][t] = l2;
    __syncthreads();
    for (int off = 1; off < 256; off <<= 1) {
        const int v0 = (t >= off) ? cnt[0][t - off] : 0;
        const int v1 = (t >= off) ? cnt[1][t - off] : 0;
        const int v2 = (t >= off) ? cnt[2][t - off] : 0;
        __syncthreads();
        cnt[0][t] += v0; cnt[1][t] += v1; cnt[2][t] += v2;
        __syncthreads();
    }
    const int tot0 = cnt[0][255], tot1 = cnt[1][255];
    int b0 = cnt[0][t] - l0;
    int b1 = tot0 + cnt[1][t] - l1;
    int b2 = tot0 + tot1 + cnt[2][t] - l2;
    for (int i = 0; i < 32; ++i) {
        const int o = t * 32 + i;
        const int v = idx[o];
        const int p = (v == 0) ? b0++ : ((v == 1) ? b1++ : b2++);
        perm[p] = o;
        pos[o]  = p;
    }
    if (t == 0) { counts[0] = tot0; counts[1] = tot0 + tot1; }
}

// c1[n] = sum_f g[f]*W2[f,n];  c2[n] = sum_f b[f]*W2[f,n] + b2[n]
__global__ void __launch_bounds__(128) colsum_partial(
    const float* __restrict__ W2, const float* __restrict__ g,
    const float* __restrict__ b, float* __restrict__ p1, float* __restrict__ p2)
{
    const int n = blockIdx.x * 128 + threadIdx.x;
    const int f0 = blockIdx.y * 64;
    float s1 = 0.0f, s2 = 0.0f;
    #pragma unroll 8
    for (int f = f0; f < f0 + 64; ++f) {
        const float w = W2[(size_t)f * HID + n];
        s1 += g[f] * w;
        s2 += b[f] * w;
    }
    p1[blockIdx.y * HID + n] = s1;
    p2[blockIdx.y * HID + n] = s2;
}

__global__ void __launch_bounds__(256) colsum_reduce(
    const float* __restrict__ p1, const float* __restrict__ p2,
    const float* __restrict__ b2, float* __restrict__ c1, float* __restrict__ c2)
{
    const int n = blockIdx.x * 256 + threadIdx.x;
    float s1 = 0.0f, s2 = 0.0f;
    #pragma unroll
    for (int q = 0; q < 64; ++q) { s1 += p1[q * HID + n]; s2 += p2[q * HID + n]; }
    c1[n] = s1;
    c2[n] = s2 + b2[n];
}

// ============================ LayerNorm: warp-per-row ============================
__global__ void __launch_bounds__(256) ln1024_warp(
    const float* __restrict__ in, const float* __restrict__ gw,
    const float* __restrict__ bw, const int* __restrict__ pos,
    __half* __restrict__ oh)
{
    const int lane = threadIdx.x & 31;
    const int row  = blockIdx.x * 8 + (threadIdx.x >> 5);
    const float4* inr = reinterpret_cast<const float4*>(in) + (size_t)row * 256;

    float4 v[8];
    float s = 0.0f, ss = 0.0f;
    #pragma unroll
    for (int i = 0; i < 8; ++i) {
        v[i] = inr[lane + i * 32];
        s  += v[i].x + v[i].y + v[i].z + v[i].w;
        ss += v[i].x * v[i].x + v[i].y * v[i].y + v[i].z * v[i].z + v[i].w * v[i].w;
    }
    #pragma unroll
    for (int off = 16; off > 0; off >>= 1) {
        s  += __shfl_xor_sync(0xffffffffu, s, off);
        ss += __shfl_xor_sync(0xffffffffu, ss, off);
    }
    const float mu  = s * (1.0f / HID);
    const float var = ss * (1.0f / HID) - mu * mu;
    const float inv = rsqrtf(var + 1e-5f);

    const float4* g4 = reinterpret_cast<const float4*>(gw);
    const float4* b4 = reinterpret_cast<const float4*>(bw);
    __half2* ohr = reinterpret_cast<__half2*>(oh) + (size_t)pos[row] * 512;
    #pragma unroll
    for (int i = 0; i < 8; ++i) {
        const int c = lane + i * 32;
        const float4 gv = g4[c], bv = b4[c], x = v[i];
        float4 o;
        o.x = (x.x - mu) * inv * gv.x + bv.x;
        o.y = (x.y - mu) * inv * gv.y + bv.y;
        o.z = (x.z - mu) * inv * gv.z + bv.z;
        o.w = (x.w - mu) * inv * gv.w + bv.w;
        ohr[c * 2 + 0] = __halves2half2(__float2half_rn(o.x), __float2half_rn(o.y));
        ohr[c * 2 + 1] = __halves2half2(__float2half_rn(o.z), __float2half_rn(o.w));
    }
}

// rowstat final reduce over 32 per-bn partials
__global__ void __launch_bounds__(256) rowstat_reduce(
    const float* __restrict__ ps, const float* __restrict__ pq,
    float* __restrict__ mu, float* __restrict__ inv)
{
    const int r = blockIdx.x * 256 + threadIdx.x;
    float s = 0.0f, q = 0.0f;
    #pragma unroll
    for (int bn = 0; bn < 32; ++bn) {
        s += ps[bn * TOKENS + r];
        q += pq[bn * TOKENS + r];
    }
    const float m = s * (1.0f / FFN);
    mu[r]  = m;
    inv[r] = rsqrtf(q * (1.0f / FFN) - m * m + 1e-5f);
}

// ============================ fp16 mma.sync GEMM mainloop (R13, proven) ============================
// CTA 128x128, BK=64, 8 warps (2x4 of 64x32), 3-stage cp.async, occ 2.
// Only change vs R13: single shared swizzle register (fragment rows are ==0 mod 8).
#define GSTAGES 3
#define GSTAGE_BYTES 32768
#define GEMM_SMEM (GSTAGES * GSTAGE_BYTES)

__device__ __forceinline__ void issue_tile(
    uint32_t dstA, uint32_t dstB,
    const __half* gA, const __half* gB, size_t gStride)
{
    #pragma unroll
    for (int p = 0; p < 4; ++p)
        CP_ASYNC16(dstA + p * 4096, gA + p * gStride);
    #pragma unroll
    for (int p = 0; p < 4; ++p)
        CP_ASYNC16(dstB + p * 4096, gB + p * gStride);
    CP_COMMIT();
}

__device__ __forceinline__ void gemm_mainloop(
    const __half* __restrict__ A, const __half* __restrict__ B,
    int K, int bm, int bn, float (&acc)[4][4][4])
{
    extern __shared__ char smem[];
    const uint32_t sbase = smem_u32(smem);
    const int tid = threadIdx.x, lane = tid & 31, wid = tid >> 5;
    const int warp_m = wid & 1, warp_n = wid >> 1;

    const int lrow = tid >> 3;
    const int lch  = tid & 7;
    const uint32_t sOffA = (uint32_t)lrow * 128 + ((lch ^ (lrow & 7)) << 4);
    const uint32_t sOffB = sOffA + 16384;
    const __half* gA = A + (size_t)(bm * 128 + lrow) * K + lch * 8;
    const __half* gB = B + (size_t)(bn * 128 + lrow) * K + lch * 8;
    const size_t gStride = (size_t)32 * K;

    // fragment rows differ by multiples of 8 -> swizzle term is row-independent
    const uint32_t sw = (uint32_t)(lane & 7) << 4;
    const uint32_t hiA = (lane & 16);
    const uint32_t hiB = ((lane & 8) << 1);
    uint32_t aAddr[4], bAddr[2];
    #pragma unroll
    for (int mt = 0; mt < 4; ++mt)
        aAddr[mt] = sbase + (warp_m * 64 + mt * 16 + (lane & 15)) * 128;
    #pragma unroll
    for (int ng = 0; ng < 2; ++ng)
        bAddr[ng] = sbase + 16384 +
                    (warp_n * 32 + ng * 16 + (lane & 7) + ((lane & 16) >> 1)) * 128;

    #pragma unroll
    for (int i = 0; i < 4; ++i)
        #pragma unroll
        for (int j = 0; j < 4; ++j)
            #pragma unroll
            for (int q = 0; q < 4; ++q) acc[i][j][q] = 0.0f;

    const int ntile = K >> 6;

    issue_tile(sbase + sOffA, sbase + sOffB, gA, gB, gStride);
    gA += 64; gB += 64;
    issue_tile(sbase + GSTAGE_BYTES + sOffA, sbase + GSTAGE_BYTES + sOffB, gA, gB, gStride);
    gA += 64; gB += 64;

    uint32_t wOff = 2 * GSTAGE_BYTES, rOff = 0;

    for (int t = 0; t < ntile; ++t) {
        if (t == ntile - 1) { CP_WAIT0(); } else { CP_WAIT1(); }
        __syncthreads();
        if (t + 2 < ntile) {
            issue_tile(sbase + wOff + sOffA, sbase + wOff + sOffB, gA, gB, gStride);
            gA += 64; gB += 64;
            wOff = (wOff == 2 * GSTAGE_BYTES) ? 0u : wOff + GSTAGE_BYTES;
        }

        #pragma unroll
        for (int j = 0; j < 4; ++j) {
            uint32_t a[4][4], b[2][4];
            #pragma unroll
            for (int mt = 0; mt < 4; ++mt)
                LDSM4(a[mt][0], a[mt][1], a[mt][2], a[mt][3],
                      aAddr[mt] + rOff + (((uint32_t)(j * 32) + hiA) ^ sw));
            #pragma unroll
            for (int ng = 0; ng < 2; ++ng)
                LDSM4(b[ng][0], b[ng][1], b[ng][2], b[ng][3],
                      bAddr[ng] + rOff + (((uint32_t)(j * 32) + hiB) ^ sw));
            #pragma unroll
            for (int mt = 0; mt < 4; ++mt)
                #pragma unroll
                for (int nt = 0; nt < 4; ++nt) {
                    const int ng = nt >> 1;
                    if (nt & 1) MMA16816F16(acc[mt][nt], a[mt][0], a[mt][1], a[mt][2], a[mt][3],
                                            b[ng][2], b[ng][3]);
                    else        MMA16816F16(acc[mt][nt], a[mt][0], a[mt][1], a[mt][2], a[mt][3],
                                            b[ng][0], b[ng][1]);
                }
        }
        rOff = (rOff == 2 * GSTAGE_BYTES) ? 0u : rOff + GSTAGE_BYTES;
    }
}

// ---- up-projection, h columns only (bn 0..31), + fused rowstat partials ----
__global__ void __launch_bounds__(256, 2) gemm_up_h(
    const __half* __restrict__ A, const __half* __restrict__ B,
    const float* __restrict__ bias, __half* __restrict__ Hh,
    float* __restrict__ ps, float* __restrict__ pq)
{
    extern __shared__ char smem[];
    float acc[4][4][4];
    const int bm = blockIdx.y, bn = blockIdx.x;
    gemm_mainloop(A, B, HID, bm, bn, acc);

    const int lane = threadIdx.x & 31, wid = threadIdx.x >> 5;
    const int warp_m = wid & 1, warp_n = wid >> 1;
    const int row0 = bm * 128 + warp_m * 64 + (lane >> 2);
    const int cw   = warp_n * 32 + (lane & 3) * 2;

    float rs[8], rq[8];
    #pragma unroll
    for (int i = 0; i < 8; ++i) { rs[i] = 0.0f; rq[i] = 0.0f; }

    #pragma unroll
    for (int mt = 0; mt < 4; ++mt) {
        #pragma unroll
        for (int nt = 0; nt < 4; ++nt) {
            const int gc = bn * 128 + cw + nt * 8;
            const float bz0 = bias[gc], bz1 = bias[gc + 1];
            float v[4];
            v[0] = gelu_exact(acc[mt][nt][0] + bz0);
            v[1] = gelu_exact(acc[mt][nt][1] + bz1);
            v[2] = gelu_exact(acc[mt][nt][2] + bz0);
            v[3] = gelu_exact(acc[mt][nt][3] + bz1);
            const __half2 hv0 = __halves2half2(__float2half_rn(v[0]), __float2half_rn(v[1]));
            const __half2 hv1 = __halves2half2(__float2half_rn(v[2]), __float2half_rn(v[3]));
            const size_t r0 = (size_t)(row0 + mt * 16);
            const size_t r1 = r0 + 8;
            *reinterpret_cast<__half2*>(Hh + r0 * FFN + gc) = hv0;
            *reinterpret_cast<__half2*>(Hh + r1 * FFN + gc) = hv1;
            const float2 f0 = __half22float2(hv0);
            const float2 f1 = __half22float2(hv1);
            rs[mt * 2 + 0] += f0.x + f0.y;
            rq[mt * 2 + 0] += f0.x * f0.x + f0.y * f0.y;
            rs[mt * 2 + 1] += f1.x + f1.y;
            rq[mt * 2 + 1] += f1.x * f1.x + f1.y * f1.y;
        }
    }

    #pragma unroll
    for (int i = 0; i < 8; ++i) {
        rs[i] += __shfl_xor_sync(0xffffffffu, rs[i], 1);
        rs[i] += __shfl_xor_sync(0xffffffffu, rs[i], 2);
        rq[i] += __shfl_xor_sync(0xffffffffu, rq[i], 1);
        rq[i] += __shfl_xor_sync(0xffffffffu, rq[i], 2);
    }
    __syncthreads();
    float* sred  = reinterpret_cast<float*>(smem);
    float* sred2 = sred + 512;
    if ((lane & 3) == 0) {
        #pragma unroll
        for (int i = 0; i < 8; ++i) {
            const int lr = warp_m * 64 + (i >> 1) * 16 + (i & 1) * 8 + (lane >> 2);
            sred [lr * 4 + warp_n] = rs[i];
            sred2[lr * 4 + warp_n] = rq[i];
        }
    }
    __syncthreads();
    if (threadIdx.x < 128) {
        const int lr = threadIdx.x;
        const float s = sred [lr * 4] + sred [lr * 4 + 1] + sred [lr * 4 + 2] + sred [lr * 4 + 3];
        const float q = sred2[lr * 4] + sred2[lr * 4 + 1] + sred2[lr * 4 + 2] + sred2[lr * 4 + 3];
        ps[bn * TOKENS + bm * 128 + lr] = s;
        pq[bn * TOKENS + bm * 128 + lr] = q;
    }
}

// ---- up-projection, adapter columns (logical bn 32..37), routed early-exit ----
__global__ void __launch_bounds__(256, 2) gemm_up_adapt(
    const __half* __restrict__ A, const __half* __restrict__ B,
    const float* __restrict__ bias, const int* __restrict__ counts,
    __half* __restrict__ T0, __half* __restrict__ T1)
{
    const int bm = blockIdx.y;
    const int bn = blockIdx.x + 32;            // 32..37
    if (bn < 34) {
        if (bm * 128 >= counts[0]) return;
    } else {
        if (bm * 128 >= counts[1] || bm * 128 + 128 <= counts[0]) return;
    }
    float acc[4][4][4];
    gemm_mainloop(A, B, HID, bm, bn, acc);

    __half* outH; int No; int colL;
    if (bn < 34) { outH = T0; No = 256; colL = (bn - 32) * 128; }
    else         { outH = T1; No = 512; colL = (bn - 34) * 128; }

    const int lane = threadIdx.x & 31, wid = threadIdx.x >> 5;
    const int warp_m = wid & 1, warp_n = wid >> 1;
    const int row0 = bm * 128 + warp_m * 64 + (lane >> 2);
    const int cw   = warp_n * 32 + (lane & 3) * 2;

    #pragma unroll
    for (int mt = 0; mt < 4; ++mt) {
        #pragma unroll
        for (int nt = 0; nt < 4; ++nt) {
            const int cc = cw + nt * 8;
            const float bz0 = bias[bn * 128 + cc];
            const float bz1 = bias[bn * 128 + cc + 1];
            float v[4];
            v[0] = gelu_exact(acc[mt][nt][0] + bz0);
            v[1] = gelu_exact(acc[mt][nt][1] + bz1);
            v[2] = gelu_exact(acc[mt][nt][2] + bz0);
            v[3] = gelu_exact(acc[mt][nt][3] + bz1);
            const int gc = colL + cc;
            const size_t r0 = (size_t)(row0 + mt * 16);
            const size_t r1 = r0 + 8;
            *reinterpret_cast<__half2*>(outH + r0 * No + gc) =
                __halves2half2(__float2half_rn(v[0]), __float2half_rn(v[1]));
            *reinterpret_cast<__half2*>(outH + r1 * No + gc) =
                __halves2half2(__float2half_rn(v[2]), __float2half_rn(v[3]));
        }
    }
}

// ---- adapter-down with routed early-exit, fp16 output ----
__global__ void __launch_bounds__(256, 2) gemm_down(
    const __half* __restrict__ A0, const __half* __restrict__ B0,
    const float* __restrict__ bias0, __half* __restrict__ C0,
    const __half* __restrict__ A1, const __half* __restrict__ B1,
    const float* __restrict__ bias1, __half* __restrict__ C1,
    const int* __restrict__ counts)
{
    const int bm = blockIdx.y, bn = blockIdx.x;
    const __half* A; const __half* B; const float* bias; __half* C; int K;
    if (blockIdx.z == 0) {
        if (bm * 128 >= counts[0]) return;
        A = A0; B = B0; bias = bias0; C = C0; K = 256;
    } else {
        if (bm * 128 >= counts[1] || bm * 128 + 128 <= counts[0]) return;
        A = A1; B = B1; bias = bias1; C = C1; K = 512;
    }
    float acc[4][4][4];
    gemm_mainloop(A, B, K, bm, bn, acc);

    const int lane = threadIdx.x & 31, wid = threadIdx.x >> 5;
    const int warp_m = wid & 1, warp_n = wid >> 1;
    const int row0 = bm * 128 + warp_m * 64 + (lane >> 2);
    const int cw   = warp_n * 32 + (lane & 3) * 2;

    #pragma unroll
    for (int mt = 0; mt < 4; ++mt) {
        #pragma unroll
        for (int nt = 0; nt < 4; ++nt) {
            const int cc = cw + nt * 8;
            const int gc = bn * 128 + cc;
            const float bz0 = bias[gc], bz1 = bias[gc + 1];
            const size_t r0 = (size_t)(row0 + mt * 16);
            const size_t r1 = r0 + 8;
            *reinterpret_cast<__half2*>(C + r0 * HID + gc) =
                __halves2half2(__float2half_rn(acc[mt][nt][0] + bz0),
                               __float2half_rn(acc[mt][nt][1] + bz1));
            *reinterpret_cast<__half2*>(C + r1 * HID + gc) =
                __halves2half2(__float2half_rn(acc[mt][nt][2] + bz0),
                               __float2half_rn(acc[mt][nt][3] + bz1));
        }
    }
}

// ---- final GEMM: LN-correction + routed combine + un-permute on store ----
__global__ void __launch_bounds__(256, 2) gemm_final(
    const __half* __restrict__ A, const __half* __restrict__ B,
    const float* __restrict__ c1, const float* __restrict__ c2,
    const float* __restrict__ mu, const float* __restrict__ inv,
    const float* __restrict__ wm, const int* __restrict__ perm,
    const int* __restrict__ counts,
    const __half* __restrict__ ad0, const __half* __restrict__ ad1,
    const __half* __restrict__ xnh, float* __restrict__ out)
{
    float acc[4][4][4];
    const int bm = blockIdx.y, bn = blockIdx.x;
    gemm_mainloop(A, B, FFN, bm, bn, acc);

    const int lane = threadIdx.x & 31, wid = threadIdx.x >> 5;
    const int warp_m = wid & 1, warp_n = wid >> 1;
    const int row0 = bm * 128 + warp_m * 64 + (lane >> 2);
    const int cw   = warp_n * 32 + (lane & 3) * 2;
    const int c0 = counts[0], c01 = counts[1];

    #pragma unroll
    for (int mt = 0; mt < 4; ++mt) {
        #pragma unroll
        for (int rr = 0; rr < 2; ++rr) {
            const int p = row0 + mt * 16 + rr * 8;      // permuted row
            const int o = perm[p];                       // original row
            const float muv = mu[p], invv = inv[p];
            const float w = wm[o], w1 = 1.0f - w;
            const __half* src = (p < c0) ? ad0 : ((p < c01) ? ad1 : xnh);
            #pragma unroll
            for (int nt = 0; nt < 4; ++nt) {
                const int gc = bn * 128 + cw + nt * 8;
                const float v0 = invv * (acc[mt][nt][rr * 2 + 0] - muv * c1[gc])     + c2[gc];
                const float v1 = invv * (acc[mt][nt][rr * 2 + 1] - muv * c1[gc + 1]) + c2[gc + 1];
                const float2 f = __half22float2(
                    *reinterpret_cast<const __half2*>(src + (size_t)p * HID + gc));
                *reinterpret_cast<float2*>(out + (size_t)o * HID + gc) =
                    make_float2(v0 * w + f.x * w1, v1 * w + f.y * w1);
            }
        }
    }
}

// ============================ launch ============================
extern "C" void kernel_launch(void* const* d_in, const int* in_sizes, int n_in,
                              void* d_out, int out_size)
{
    const float* x        = (const float*)d_in[0];
    const float* wm       = (const float*)d_in[1];
    const int*   widx     = (const int*)  d_in[2];
    const float* ln_in_g  = (const float*)d_in[3];
    const float* ln_in_b  = (const float*)d_in[4];
    const float* W1       = (const float*)d_in[5];
    const float* b1       = (const float*)d_in[6];
    const float* ln_h_g   = (const float*)d_in[7];
    const float* ln_h_b   = (const float*)d_in[8];
    const float* W2       = (const float*)d_in[9];
    const float* b2       = (const float*)d_in[10];
    const float* a256_w1  = (const float*)d_in[11];
    const float* a256_b1  = (const float*)d_in[12];
    const float* a256_w2  = (const float*)d_in[13];
    const float* a256_b2  = (const float*)d_in[14];
    const float* a512_w1  = (const float*)d_in[15];
    const float* a512_b1  = (const float*)d_in[16];
    const float* a512_w2  = (const float*)d_in[17];
    const float* a512_b2  = (const float*)d_in[18];
    float* out = (float*)d_out;

    cudaFuncSetAttribute(gemm_up_h,     cudaFuncAttributeMaxDynamicSharedMemorySize, GEMM_SMEM);
    cudaFuncSetAttribute(gemm_up_adapt, cudaFuncAttributeMaxDynamicSharedMemorySize, GEMM_SMEM);
    cudaFuncSetAttribute(gemm_down,     cudaFuncAttributeMaxDynamicSharedMemorySize, GEMM_SMEM);
    cudaFuncSetAttribute(gemm_final,    cudaFuncAttributeMaxDynamicSharedMemorySize, GEMM_SMEM);

    float *bup, *mu, *inv, *c1, *c2, *p1, *p2, *ps, *pq;
    __half *xnh, *hh, *t0h, *t1h, *wup, *w2t, *a2t, *b2t, *ad0, *ad1;
    int *perm, *pos, *counts;
    cudaGetSymbolAddress((void**)&ad0,   g_ad0);
    cudaGetSymbolAddress((void**)&ad1,   g_ad1);
    cudaGetSymbolAddress((void**)&bup,   g_bup);
    cudaGetSymbolAddress((void**)&mu,    g_mu);
    cudaGetSymbolAddress((void**)&inv,   g_inv);
    cudaGetSymbolAddress((void**)&c1,    g_c1);
    cudaGetSymbolAddress((void**)&c2,    g_c2);
    cudaGetSymbolAddress((void**)&p1,    g_p1);
    cudaGetSymbolAddress((void**)&p2,    g_p2);
    cudaGetSymbolAddress((void**)&ps,    g_ps);
    cudaGetSymbolAddress((void**)&pq,    g_pq);
    cudaGetSymbolAddress((void**)&xnh,   g_xnh);
    cudaGetSymbolAddress((void**)&hh,    g_hh);
    cudaGetSymbolAddress((void**)&t0h,   g_t0h);
    cudaGetSymbolAddress((void**)&t1h,   g_t1h);
    cudaGetSymbolAddress((void**)&wup,   g_wup);
    cudaGetSymbolAddress((void**)&w2t,   g_w2t);
    cudaGetSymbolAddress((void**)&a2t,   g_a2t);
    cudaGetSymbolAddress((void**)&b2t,   g_b2t);
    cudaGetSymbolAddress((void**)&perm,  g_perm);
    cudaGetSymbolAddress((void**)&pos,   g_pos);
    cudaGetSymbolAddress((void**)&counts, g_counts);

    static cudaStream_t s2 = nullptr;
    static cudaEvent_t evFork = nullptr, evW = nullptr, evLn = nullptr, evSide = nullptr;
    if (s2 == nullptr) {
        cudaStreamCreateWithFlags(&s2, cudaStreamNonBlocking);
        cudaEventCreateWithFlags(&evFork, cudaEventDisableTiming);
        cudaEventCreateWithFlags(&evW,    cudaEventDisableTiming);
        cudaEventCreateWithFlags(&evLn,   cudaEventDisableTiming);
        cudaEventCreateWithFlags(&evSide, cudaEventDisableTiming);
    }

    // ---- fork side stream: all weight prep ----
    cudaEventRecord(evFork, 0);
    cudaStreamWaitEvent(s2, evFork, 0);
    transpose_w1<<<dim3(FFN / 32, HID / 32), 256, 0, s2>>>(W1, wup);
    prep_weights<<<dim3(32, 32, 5), 256, 0, s2>>>(a256_w1, a256_w2, a512_w1, a512_w2,
                                                  wup, a2t, b2t,
                                                  b1, a256_b1, a512_b1, bup);
    cudaEventRecord(evW, s2);      // wup/bup (and a2t/b2t in-stream) ready
    transpose_w2<<<dim3(HID / 32, FFN / 32), 256, 0, s2>>>(W2, ln_h_g, w2t);
    colsum_partial<<<dim3(HID / 128, 64), 128, 0, s2>>>(W2, ln_h_g, ln_h_b, p1, p2);
    colsum_reduce<<<HID / 256, 256, 0, s2>>>(p1, p2, b2, c1, c2);

    // ---- main chain: perm -> LN ----
    perm_kernel<<<1, 256>>>(widx, perm, pos, counts);
    ln1024_warp<<<TOKENS / 8, 256>>>(x, ln_in_g, ln_in_b, pos, xnh);
    cudaEventRecord(evLn, 0);

    // ---- side stream: adapter up + adapter down (overlaps with up_h) ----
    cudaStreamWaitEvent(s2, evLn, 0);
    gemm_up_adapt<<<dim3(6, TOKENS / 128), 256, GEMM_SMEM, s2>>>(
        xnh, wup, bup, counts, t0h, t1h);
    gemm_down<<<dim3(HID / 128, TOKENS / 128, 2), 256, GEMM_SMEM, s2>>>(
        t0h, a2t, a256_b2, ad0, t1h, b2t, a512_b2, ad1, counts);
    cudaEventRecord(evSide, s2);

    // ---- main chain: big up-projection (fused rowstat partials), reduce ----
    cudaStreamWaitEvent(0, evW, 0);
    gemm_up_h<<<dim3(FFN / 128, TOKENS / 128), 256, GEMM_SMEM>>>(xnh, wup, bup, hh, ps, pq);
    rowstat_reduce<<<TOKENS / 256, 256>>>(ps, pq, mu, inv);

    // ---- join, final ----
    cudaStreamWaitEvent(0, evSide, 0);
    gemm_final<<<dim3(HID / 128, TOKENS / 128), 256, GEMM_SMEM>>>(
        hh, w2t, c1, c2, mu, inv, wm, perm, counts, ad0, ad1, xnh, out);
}

// round 16
// speedup vs baseline: 1.0314x; 1.0091x over previous
#include <cuda_runtime.h>
#include <cuda_fp16.h>
#include <math.h>
#include <stdint.h>

#define TOKENS 8192
#define HID    1024
#define FFN    4096
#define NUP    4864      // 4096 + 256 + 512 fused up-projection width

// ============================ scratch (device globals) ============================
__device__ __half g_xnh[TOKENS * HID];         // permuted row space
__device__ __half g_hh[TOKENS * FFN];          // permuted
__device__ float  g_mu[TOKENS], g_inv[TOKENS]; // permuted
__device__ __half g_ad0[TOKENS * HID], g_ad1[TOKENS * HID];   // permuted, fp16
__device__ __half g_t0h[TOKENS * 256];         // permuted
__device__ __half g_t1h[TOKENS * 512];         // permuted
__device__ __half g_wup[NUP * HID];
__device__ float  g_bup[NUP];
__device__ __half g_w2t[HID * FFN];            // (ln_h_g ∘ W2)^T fp16
__device__ __half g_a2t[HID * 256];
__device__ __half g_b2t[HID * 512];
__device__ float  g_c1[HID], g_c2[HID];
__device__ float  g_p1[256 * HID], g_p2[256 * HID];
__device__ float  g_ps[32 * TOKENS], g_pq[32 * TOKENS];   // rowstat partials per bn
__device__ int    g_perm[TOKENS];              // new(p) -> old(o)
__device__ int    g_pos[TOKENS];               // old(o) -> new(p)
__device__ int    g_counts[2];                 // c0, c0+c1

__device__ __forceinline__ float gelu_exact(float x) {
    return 0.5f * x * (1.0f + erff(x * 0.7071067811865475f));
}
__device__ __forceinline__ uint32_t smem_u32(const void* p) {
    uint32_t a;
    asm("{ .reg .u64 t; cvta.to.shared.u64 t, %1; cvt.u32.u64 %0, t; }" : "=r"(a) : "l"(p));
    return a;
}

#define CP_ASYNC16(s, g) \
    asm volatile("cp.async.cg.shared.global [%0], [%1], 16;" :: "r"(s), "l"(g))
#define CP_COMMIT() asm volatile("cp.async.commit_group;")
#define CP_WAIT1()  asm volatile("cp.async.wait_group 1;")
#define CP_WAIT0()  asm volatile("cp.async.wait_group 0;")

#define LDSM4(r0, r1, r2, r3, addr) \
    asm volatile("ldmatrix.sync.aligned.m8n8.x4.shared.b16 {%0,%1,%2,%3}, [%4];" \
                 : "=r"(r0), "=r"(r1), "=r"(r2), "=r"(r3) : "r"(addr))

#define MMA16816F16(d, a0, a1, a2, a3, b0, b1) \
    asm volatile("mma.sync.aligned.m16n8k16.row.col.f32.f16.f16.f32 " \
                 "{%0,%1,%2,%3}, {%4,%5,%6,%7}, {%8,%9}, {%0,%1,%2,%3};" \
                 : "+f"((d)[0]), "+f"((d)[1]), "+f"((d)[2]), "+f"((d)[3]) \
                 : "r"(a0), "r"(a1), "r"(a2), "r"(a3), "r"(b0), "r"(b1))

// ============================ weight prep ============================
__device__ __forceinline__ void do_transpose(
    const float* __restrict__ W, int K, int N, __half* __restrict__ T, int rowOff,
    const float* __restrict__ scale)
{
    __shared__ float s[32][33];
    const int n0 = blockIdx.x * 32, k0 = blockIdx.y * 32;
    if (n0 >= N || k0 >= K) return;
    const int tr = threadIdx.x >> 3;
    const int tc = (threadIdx.x & 7) * 4;
    const float4 v = *reinterpret_cast<const float4*>(W + (size_t)(k0 + tr) * N + n0 + tc);
    s[tr][tc + 0] = v.x; s[tr][tc + 1] = v.y; s[tr][tc + 2] = v.z; s[tr][tc + 3] = v.w;
    __syncthreads();
    const size_t off = (size_t)(rowOff + n0 + tr) * K + k0 + tc;
    #pragma unroll
    for (int q = 0; q < 2; ++q) {
        float x0 = s[tc + q * 2 + 0][tr];
        float x1 = s[tc + q * 2 + 1][tr];
        if (scale) {
            x0 *= scale[k0 + tc + q * 2 + 0];
            x1 *= scale[k0 + tc + q * 2 + 1];
        }
        *reinterpret_cast<__half2*>(T + off + q * 2) =
            __halves2half2(__float2half_rn(x0), __float2half_rn(x1));
    }
}

__global__ void __launch_bounds__(256) transpose_w1(
    const float* __restrict__ W1, __half* wup)
{
    do_transpose(W1, HID, FFN, wup, 0, nullptr);
}

__global__ void __launch_bounds__(256) transpose_w2(
    const float* __restrict__ W2, const float* __restrict__ lnhg, __half* w2t)
{
    do_transpose(W2, FFN, HID, w2t, 0, lnhg);
}

__global__ void __launch_bounds__(256) prep_weights(
    const float* __restrict__ aw1, const float* __restrict__ aw2,
    const float* __restrict__ bw1, const float* __restrict__ bw2,
    __half* wup, __half* a2t, __half* b2t,
    const float* __restrict__ b1, const float* __restrict__ ab1,
    const float* __restrict__ bb1, float* __restrict__ bup)
{
    switch (blockIdx.z) {
        case 0: do_transpose(aw1, HID, 256, wup, 4096, nullptr); break;
        case 1: do_transpose(aw2, 256, HID, a2t, 0, nullptr);    break;
        case 2: do_transpose(bw1, HID, 512, wup, 4352, nullptr); break;
        case 3: do_transpose(bw2, 512, HID, b2t, 0, nullptr);    break;
        default: {
            const int i = (blockIdx.y * 32 + blockIdx.x) * 256 + threadIdx.x;
            if (i < NUP) {
                float v;
                if (i < 4096) v = b1[i];
                else if (i < 4352) v = ab1[i - 4096];
                else v = bb1[i - 4352];
                bup[i] = v;
            }
            break;
        }
    }
}

// stable counting sort of 8192 idx values into perm/pos, 1 block x 256 threads
__global__ void __launch_bounds__(256) perm_kernel(
    const int* __restrict__ idx, int* __restrict__ perm,
    int* __restrict__ pos, int* __restrict__ counts)
{
    __shared__ int cnt[3][256];
    const int t = threadIdx.x;
    int l0 = 0, l1 = 0, l2 = 0;
    for (int i = 0; i < 32; ++i) {
        const int v = idx[t * 32 + i];
        l0 += (v == 0); l1 += (v == 1); l2 += (v == 2);
    }
    cnt[0][t] = l0; cnt[1][t] = l1; cnt[2][t] = l2;
    __syncthreads();
    for (int off = 1; off < 256; off <<= 1) {
        const int v0 = (t >= off) ? cnt[0][t - off] : 0;
        const int v1 = (t >= off) ? cnt[1][t - off] : 0;
        const int v2 = (t >= off) ? cnt[2][t - off] : 0;
        __syncthreads();
        cnt[0][t] += v0; cnt[1][t] += v1; cnt[2][t] += v2;
        __syncthreads();
    }
    const int tot0 = cnt[0][255], tot1 = cnt[1][255];
    int b0 = cnt[0][t] - l0;
    int b1 = tot0 + cnt[1][t] - l1;
    int b2 = tot0 + tot1 + cnt[2][t] - l2;
    for (int i = 0; i < 32; ++i) {
        const int o = t * 32 + i;
        const int v = idx[o];
        const int p = (v == 0) ? b0++ : ((v == 1) ? b1++ : b2++);
        perm[p] = o;
        pos[o]  = p;
    }
    if (t == 0) { counts[0] = tot0; counts[1] = tot0 + tot1; }
}

// c1[n] = sum_f g[f]*W2[f,n];  c2[n] = sum_f b[f]*W2[f,n] + b2[n]
// 4x parallelism vs R13: 16 f-rows per block, 256 y-blocks
__global__ void __launch_bounds__(128) colsum_partial(
    const float* __restrict__ W2, const float* __restrict__ g,
    const float* __restrict__ b, float* __restrict__ p1, float* __restrict__ p2)
{
    const int n = blockIdx.x * 128 + threadIdx.x;
    const int f0 = blockIdx.y * 16;
    float s1 = 0.0f, s2 = 0.0f;
    #pragma unroll
    for (int f = f0; f < f0 + 16; ++f) {
        const float w = W2[(size_t)f * HID + n];
        s1 += g[f] * w;
        s2 += b[f] * w;
    }
    p1[blockIdx.y * HID + n] = s1;
    p2[blockIdx.y * HID + n] = s2;
}

__global__ void __launch_bounds__(256) colsum_reduce(
    const float* __restrict__ p1, const float* __restrict__ p2,
    const float* __restrict__ b2, float* __restrict__ c1, float* __restrict__ c2)
{
    const int n = blockIdx.x * 256 + threadIdx.x;
    float s1 = 0.0f, s2 = 0.0f;
    #pragma unroll
    for (int q = 0; q < 256; ++q) { s1 += p1[q * HID + n]; s2 += p2[q * HID + n]; }
    c1[n] = s1;
    c2[n] = s2 + b2[n];
}

// ============================ LayerNorm: warp-per-row ============================
__global__ void __launch_bounds__(256) ln1024_warp(
    const float* __restrict__ in, const float* __restrict__ gw,
    const float* __restrict__ bw, const int* __restrict__ pos,
    __half* __restrict__ oh)
{
    const int lane = threadIdx.x & 31;
    const int row  = blockIdx.x * 8 + (threadIdx.x >> 5);
    const float4* inr = reinterpret_cast<const float4*>(in) + (size_t)row * 256;

    float4 v[8];
    float s = 0.0f, ss = 0.0f;
    #pragma unroll
    for (int i = 0; i < 8; ++i) {
        v[i] = inr[lane + i * 32];
        s  += v[i].x + v[i].y + v[i].z + v[i].w;
        ss += v[i].x * v[i].x + v[i].y * v[i].y + v[i].z * v[i].z + v[i].w * v[i].w;
    }
    #pragma unroll
    for (int off = 16; off > 0; off >>= 1) {
        s  += __shfl_xor_sync(0xffffffffu, s, off);
        ss += __shfl_xor_sync(0xffffffffu, ss, off);
    }
    const float mu  = s * (1.0f / HID);
    const float var = ss * (1.0f / HID) - mu * mu;
    const float inv = rsqrtf(var + 1e-5f);

    const float4* g4 = reinterpret_cast<const float4*>(gw);
    const float4* b4 = reinterpret_cast<const float4*>(bw);
    __half2* ohr = reinterpret_cast<__half2*>(oh) + (size_t)pos[row] * 512;
    #pragma unroll
    for (int i = 0; i < 8; ++i) {
        const int c = lane + i * 32;
        const float4 gv = g4[c], bv = b4[c], x = v[i];
        float4 o;
        o.x = (x.x - mu) * inv * gv.x + bv.x;
        o.y = (x.y - mu) * inv * gv.y + bv.y;
        o.z = (x.z - mu) * inv * gv.z + bv.z;
        o.w = (x.w - mu) * inv * gv.w + bv.w;
        ohr[c * 2 + 0] = __halves2half2(__float2half_rn(o.x), __float2half_rn(o.y));
        ohr[c * 2 + 1] = __halves2half2(__float2half_rn(o.z), __float2half_rn(o.w));
    }
}

// rowstat final reduce over 32 per-bn partials
__global__ void __launch_bounds__(256) rowstat_reduce(
    const float* __restrict__ ps, const float* __restrict__ pq,
    float* __restrict__ mu, float* __restrict__ inv)
{
    const int r = blockIdx.x * 256 + threadIdx.x;
    float s = 0.0f, q = 0.0f;
    #pragma unroll
    for (int bn = 0; bn < 32; ++bn) {
        s += ps[bn * TOKENS + r];
        q += pq[bn * TOKENS + r];
    }
    const float m = s * (1.0f / FFN);
    mu[r]  = m;
    inv[r] = rsqrtf(q * (1.0f / FFN) - m * m + 1e-5f);
}

// ============================ fp16 mma.sync GEMM mainloop (R13 bit-exact) ============================
// CTA 128x128, BK=64, 8 warps (2x4 of 64x32), 3-stage cp.async, occ 2.
#define GSTAGES 3
#define GSTAGE_BYTES 32768
#define GEMM_SMEM (GSTAGES * GSTAGE_BYTES)

__device__ __forceinline__ void issue_tile(
    uint32_t dstA, uint32_t dstB,
    const __half* gA, const __half* gB, size_t gStride)
{
    #pragma unroll
    for (int p = 0; p < 4; ++p)
        CP_ASYNC16(dstA + p * 4096, gA + p * gStride);
    #pragma unroll
    for (int p = 0; p < 4; ++p)
        CP_ASYNC16(dstB + p * 4096, gB + p * gStride);
    CP_COMMIT();
}

__device__ __forceinline__ void gemm_mainloop(
    const __half* __restrict__ A, const __half* __restrict__ B,
    int K, int bm, int bn, float (&acc)[4][4][4])
{
    extern __shared__ char smem[];
    const uint32_t sbase = smem_u32(smem);
    const int tid = threadIdx.x, lane = tid & 31, wid = tid >> 5;
    const int warp_m = wid & 1, warp_n = wid >> 1;

    const int lrow = tid >> 3;
    const int lch  = tid & 7;
    const uint32_t sOffA = (uint32_t)lrow * 128 + ((lch ^ (lrow & 7)) << 4);
    const uint32_t sOffB = sOffA + 16384;
    const __half* gA = A + (size_t)(bm * 128 + lrow) * K + lch * 8;
    const __half* gB = B + (size_t)(bn * 128 + lrow) * K + lch * 8;
    const size_t gStride = (size_t)32 * K;

    uint32_t aAddr[4], bAddr[2], aSw[4], bSw[2];
    const uint32_t hiA = (lane & 16);
    const uint32_t hiB = ((lane & 8) << 1);
    #pragma unroll
    for (int mt = 0; mt < 4; ++mt) {
        const int r = warp_m * 64 + mt * 16 + (lane & 15);
        aAddr[mt] = sbase + r * 128;
        aSw[mt]   = ((r & 7) << 4);
    }
    #pragma unroll
    for (int ng = 0; ng < 2; ++ng) {
        const int r = warp_n * 32 + ng * 16 + (lane & 7) + ((lane & 16) >> 1);
        bAddr[ng] = sbase + 16384 + r * 128;
        bSw[ng]   = ((r & 7) << 4);
    }

    #pragma unroll
    for (int i = 0; i < 4; ++i)
        #pragma unroll
        for (int j = 0; j < 4; ++j)
            #pragma unroll
            for (int q = 0; q < 4; ++q) acc[i][j][q] = 0.0f;

    const int ntile = K >> 6;

    issue_tile(sbase + sOffA, sbase + sOffB, gA, gB, gStride);
    gA += 64; gB += 64;
    issue_tile(sbase + GSTAGE_BYTES + sOffA, sbase + GSTAGE_BYTES + sOffB, gA, gB, gStride);
    gA += 64; gB += 64;

    uint32_t wOff = 2 * GSTAGE_BYTES, rOff = 0;

    for (int t = 0; t < ntile; ++t) {
        if (t == ntile - 1) { CP_WAIT0(); } else { CP_WAIT1(); }
        __syncthreads();
        if (t + 2 < ntile) {
            issue_tile(sbase + wOff + sOffA, sbase + wOff + sOffB, gA, gB, gStride);
            gA += 64; gB += 64;
            wOff = (wOff == 2 * GSTAGE_BYTES) ? 0u : wOff + GSTAGE_BYTES;
        }

        #pragma unroll
        for (int j = 0; j < 4; ++j) {
            uint32_t a[4][4], b[2][4];
            #pragma unroll
            for (int mt = 0; mt < 4; ++mt)
                LDSM4(a[mt][0], a[mt][1], a[mt][2], a[mt][3],
                      aAddr[mt] + rOff + (((uint32_t)(j * 32) + hiA) ^ aSw[mt]));
            #pragma unroll
            for (int ng = 0; ng < 2; ++ng)
                LDSM4(b[ng][0], b[ng][1], b[ng][2], b[ng][3],
                      bAddr[ng] + rOff + (((uint32_t)(j * 32) + hiB) ^ bSw[ng]));
            #pragma unroll
            for (int mt = 0; mt < 4; ++mt)
                #pragma unroll
                for (int nt = 0; nt < 4; ++nt) {
                    const int ng = nt >> 1;
                    if (nt & 1) MMA16816F16(acc[mt][nt], a[mt][0], a[mt][1], a[mt][2], a[mt][3],
                                            b[ng][2], b[ng][3]);
                    else        MMA16816F16(acc[mt][nt], a[mt][0], a[mt][1], a[mt][2], a[mt][3],
                                            b[ng][0], b[ng][1]);
                }
        }
        rOff = (rOff == 2 * GSTAGE_BYTES) ? 0u : rOff + GSTAGE_BYTES;
    }
}

// ---- up-projection, h columns only (bn 0..31), + fused rowstat partials ----
__global__ void __launch_bounds__(256, 2) gemm_up_h(
    const __half* __restrict__ A, const __half* __restrict__ B,
    const float* __restrict__ bias, __half* __restrict__ Hh,
    float* __restrict__ ps, float* __restrict__ pq)
{
    extern __shared__ char smem[];
    float acc[4][4][4];
    const int bm = blockIdx.y, bn = blockIdx.x;
    gemm_mainloop(A, B, HID, bm, bn, acc);

    const int lane = threadIdx.x & 31, wid = threadIdx.x >> 5;
    const int warp_m = wid & 1, warp_n = wid >> 1;
    const int row0 = bm * 128 + warp_m * 64 + (lane >> 2);
    const int cw   = warp_n * 32 + (lane & 3) * 2;

    float rs[8], rq[8];
    #pragma unroll
    for (int i = 0; i < 8; ++i) { rs[i] = 0.0f; rq[i] = 0.0f; }

    #pragma unroll
    for (int mt = 0; mt < 4; ++mt) {
        #pragma unroll
        for (int nt = 0; nt < 4; ++nt) {
            const int gc = bn * 128 + cw + nt * 8;
            const float bz0 = bias[gc], bz1 = bias[gc + 1];
            float v[4];
            v[0] = gelu_exact(acc[mt][nt][0] + bz0);
            v[1] = gelu_exact(acc[mt][nt][1] + bz1);
            v[2] = gelu_exact(acc[mt][nt][2] + bz0);
            v[3] = gelu_exact(acc[mt][nt][3] + bz1);
            const __half2 hv0 = __halves2half2(__float2half_rn(v[0]), __float2half_rn(v[1]));
            const __half2 hv1 = __halves2half2(__float2half_rn(v[2]), __float2half_rn(v[3]));
            const size_t r0 = (size_t)(row0 + mt * 16);
            const size_t r1 = r0 + 8;
            *reinterpret_cast<__half2*>(Hh + r0 * FFN + gc) = hv0;
            *reinterpret_cast<__half2*>(Hh + r1 * FFN + gc) = hv1;
            const float2 f0 = __half22float2(hv0);
            const float2 f1 = __half22float2(hv1);
            rs[mt * 2 + 0] += f0.x + f0.y;
            rq[mt * 2 + 0] += f0.x * f0.x + f0.y * f0.y;
            rs[mt * 2 + 1] += f1.x + f1.y;
            rq[mt * 2 + 1] += f1.x * f1.x + f1.y * f1.y;
        }
    }

    #pragma unroll
    for (int i = 0; i < 8; ++i) {
        rs[i] += __shfl_xor_sync(0xffffffffu, rs[i], 1);
        rs[i] += __shfl_xor_sync(0xffffffffu, rs[i], 2);
        rq[i] += __shfl_xor_sync(0xffffffffu, rq[i], 1);
        rq[i] += __shfl_xor_sync(0xffffffffu, rq[i], 2);
    }
    __syncthreads();
    float* sred  = reinterpret_cast<float*>(smem);
    float* sred2 = sred + 512;
    if ((lane & 3) == 0) {
        #pragma unroll
        for (int i = 0; i < 8; ++i) {
            const int lr = warp_m * 64 + (i >> 1) * 16 + (i & 1) * 8 + (lane >> 2);
            sred [lr * 4 + warp_n] = rs[i];
            sred2[lr * 4 + warp_n] = rq[i];
        }
    }
    __syncthreads();
    if (threadIdx.x < 128) {
        const int lr = threadIdx.x;
        const float s = sred [lr * 4] + sred [lr * 4 + 1] + sred [lr * 4 + 2] + sred [lr * 4 + 3];
        const float q = sred2[lr * 4] + sred2[lr * 4 + 1] + sred2[lr * 4 + 2] + sred2[lr * 4 + 3];
        ps[bn * TOKENS + bm * 128 + lr] = s;
        pq[bn * TOKENS + bm * 128 + lr] = q;
    }
}

// ---- up-projection, adapter columns (logical bn 32..37), routed early-exit ----
__global__ void __launch_bounds__(256, 2) gemm_up_adapt(
    const __half* __restrict__ A, const __half* __restrict__ B,
    const float* __restrict__ bias, const int* __restrict__ counts,
    __half* __restrict__ T0, __half* __restrict__ T1)
{
    const int bm = blockIdx.y;
    const int bn = blockIdx.x + 32;            // 32..37
    if (bn < 34) {
        if (bm * 128 >= counts[0]) return;
    } else {
        if (bm * 128 >= counts[1] || bm * 128 + 128 <= counts[0]) return;
    }
    float acc[4][4][4];
    gemm_mainloop(A, B, HID, bm, bn, acc);

    __half* outH; int No; int colL;
    if (bn < 34) { outH = T0; No = 256; colL = (bn - 32) * 128; }
    else         { outH = T1; No = 512; colL = (bn - 34) * 128; }

    const int lane = threadIdx.x & 31, wid = threadIdx.x >> 5;
    const int warp_m = wid & 1, warp_n = wid >> 1;
    const int row0 = bm * 128 + warp_m * 64 + (lane >> 2);
    const int cw   = warp_n * 32 + (lane & 3) * 2;

    #pragma unroll
    for (int mt = 0; mt < 4; ++mt) {
        #pragma unroll
        for (int nt = 0; nt < 4; ++nt) {
            const int cc = cw + nt * 8;
            const float bz0 = bias[bn * 128 + cc];
            const float bz1 = bias[bn * 128 + cc + 1];
            float v[4];
            v[0] = gelu_exact(acc[mt][nt][0] + bz0);
            v[1] = gelu_exact(acc[mt][nt][1] + bz1);
            v[2] = gelu_exact(acc[mt][nt][2] + bz0);
            v[3] = gelu_exact(acc[mt][nt][3] + bz1);
            const int gc = colL + cc;
            const size_t r0 = (size_t)(row0 + mt * 16);
            const size_t r1 = r0 + 8;
            *reinterpret_cast<__half2*>(outH + r0 * No + gc) =
                __halves2half2(__float2half_rn(v[0]), __float2half_rn(v[1]));
            *reinterpret_cast<__half2*>(outH + r1 * No + gc) =
                __halves2half2(__float2half_rn(v[2]), __float2half_rn(v[3]));
        }
    }
}

// ---- adapter-down with routed early-exit, fp16 output ----
__global__ void __launch_bounds__(256, 2) gemm_down(
    const __half* __restrict__ A0, const __half* __restrict__ B0,
    const float* __restrict__ bias0, __half* __restrict__ C0,
    const __half* __restrict__ A1, const __half* __restrict__ B1,
    const float* __restrict__ bias1, __half* __restrict__ C1,
    const int* __restrict__ counts)
{
    const int bm = blockIdx.y, bn = blockIdx.x;
    const __half* A; const __half* B; const float* bias; __half* C; int K;
    if (blockIdx.z == 0) {
        if (bm * 128 >= counts[0]) return;
        A = A0; B = B0; bias = bias0; C = C0; K = 256;
    } else {
        if (bm * 128 >= counts[1] || bm * 128 + 128 <= counts[0]) return;
        A = A1; B = B1; bias = bias1; C = C1; K = 512;
    }
    float acc[4][4][4];
    gemm_mainloop(A, B, K, bm, bn, acc);

    const int lane = threadIdx.x & 31, wid = threadIdx.x >> 5;
    const int warp_m = wid & 1, warp_n = wid >> 1;
    const int row0 = bm * 128 + warp_m * 64 + (lane >> 2);
    const int cw   = warp_n * 32 + (lane & 3) * 2;

    #pragma unroll
    for (int mt = 0; mt < 4; ++mt) {
        #pragma unroll
        for (int nt = 0; nt < 4; ++nt) {
            const int cc = cw + nt * 8;
            const int gc = bn * 128 + cc;
            const float bz0 = bias[gc], bz1 = bias[gc + 1];
            const size_t r0 = (size_t)(row0 + mt * 16);
            const size_t r1 = r0 + 8;
            *reinterpret_cast<__half2*>(C + r0 * HID + gc) =
                __halves2half2(__float2half_rn(acc[mt][nt][0] + bz0),
                               __float2half_rn(acc[mt][nt][1] + bz1));
            *reinterpret_cast<__half2*>(C + r1 * HID + gc) =
                __halves2half2(__float2half_rn(acc[mt][nt][2] + bz0),
                               __float2half_rn(acc[mt][nt][3] + bz1));
        }
    }
}

// ---- final GEMM: LN-correction + routed combine + un-permute on store ----
__global__ void __launch_bounds__(256, 2) gemm_final(
    const __half* __restrict__ A, const __half* __restrict__ B,
    const float* __restrict__ c1, const float* __restrict__ c2,
    const float* __restrict__ mu, const float* __restrict__ inv,
    const float* __restrict__ wm, const int* __restrict__ perm,
    const int* __restrict__ counts,
    const __half* __restrict__ ad0, const __half* __restrict__ ad1,
    const __half* __restrict__ xnh, float* __restrict__ out)
{
    float acc[4][4][4];
    const int bm = blockIdx.y, bn = blockIdx.x;
    gemm_mainloop(A, B, FFN, bm, bn, acc);

    const int lane = threadIdx.x & 31, wid = threadIdx.x >> 5;
    const int warp_m = wid & 1, warp_n = wid >> 1;
    const int row0 = bm * 128 + warp_m * 64 + (lane >> 2);
    const int cw   = warp_n * 32 + (lane & 3) * 2;
    const int c0 = counts[0], c01 = counts[1];

    #pragma unroll
    for (int mt = 0; mt < 4; ++mt) {
        #pragma unroll
        for (int rr = 0; rr < 2; ++rr) {
            const int p = row0 + mt * 16 + rr * 8;      // permuted row
            const int o = perm[p];                       // original row
            const float muv = mu[p], invv = inv[p];
            const float w = wm[o], w1 = 1.0f - w;
            const __half* src = (p < c0) ? ad0 : ((p < c01) ? ad1 : xnh);
            #pragma unroll
            for (int nt = 0; nt < 4; ++nt) {
                const int gc = bn * 128 + cw + nt * 8;
                const float v0 = invv * (acc[mt][nt][rr * 2 + 0] - muv * c1[gc])     + c2[gc];
                const float v1 = invv * (acc[mt][nt][rr * 2 + 1] - muv * c1[gc + 1]) + c2[gc + 1];
                const float2 f = __half22float2(
                    *reinterpret_cast<const __half2*>(src + (size_t)p * HID + gc));
                *reinterpret_cast<float2*>(out + (size_t)o * HID + gc) =
                    make_float2(v0 * w + f.x * w1, v1 * w + f.y * w1);
            }
        }
    }
}

// ============================ launch ============================
extern "C" void kernel_launch(void* const* d_in, const int* in_sizes, int n_in,
                              void* d_out, int out_size)
{
    const float* x        = (const float*)d_in[0];
    const float* wm       = (const float*)d_in[1];
    const int*   widx     = (const int*)  d_in[2];
    const float* ln_in_g  = (const float*)d_in[3];
    const float* ln_in_b  = (const float*)d_in[4];
    const float* W1       = (const float*)d_in[5];
    const float* b1       = (const float*)d_in[6];
    const float* ln_h_g   = (const float*)d_in[7];
    const float* ln_h_b   = (const float*)d_in[8];
    const float* W2       = (const float*)d_in[9];
    const float* b2       = (const float*)d_in[10];
    const float* a256_w1  = (const float*)d_in[11];
    const float* a256_b1  = (const float*)d_in[12];
    const float* a256_w2  = (const float*)d_in[13];
    const float* a256_b2  = (const float*)d_in[14];
    const float* a512_w1  = (const float*)d_in[15];
    const float* a512_b1  = (const float*)d_in[16];
    const float* a512_w2  = (const float*)d_in[17];
    const float* a512_b2  = (const float*)d_in[18];
    float* out = (float*)d_out;

    cudaFuncSetAttribute(gemm_up_h,     cudaFuncAttributeMaxDynamicSharedMemorySize, GEMM_SMEM);
    cudaFuncSetAttribute(gemm_up_adapt, cudaFuncAttributeMaxDynamicSharedMemorySize, GEMM_SMEM);
    cudaFuncSetAttribute(gemm_down,     cudaFuncAttributeMaxDynamicSharedMemorySize, GEMM_SMEM);
    cudaFuncSetAttribute(gemm_final,    cudaFuncAttributeMaxDynamicSharedMemorySize, GEMM_SMEM);

    float *bup, *mu, *inv, *c1, *c2, *p1, *p2, *ps, *pq;
    __half *xnh, *hh, *t0h, *t1h, *wup, *w2t, *a2t, *b2t, *ad0, *ad1;
    int *perm, *pos, *counts;
    cudaGetSymbolAddress((void**)&ad0,   g_ad0);
    cudaGetSymbolAddress((void**)&ad1,   g_ad1);
    cudaGetSymbolAddress((void**)&bup,   g_bup);
    cudaGetSymbolAddress((void**)&mu,    g_mu);
    cudaGetSymbolAddress((void**)&inv,   g_inv);
    cudaGetSymbolAddress((void**)&c1,    g_c1);
    cudaGetSymbolAddress((void**)&c2,    g_c2);
    cudaGetSymbolAddress((void**)&p1,    g_p1);
    cudaGetSymbolAddress((void**)&p2,    g_p2);
    cudaGetSymbolAddress((void**)&ps,    g_ps);
    cudaGetSymbolAddress((void**)&pq,    g_pq);
    cudaGetSymbolAddress((void**)&xnh,   g_xnh);
    cudaGetSymbolAddress((void**)&hh,    g_hh);
    cudaGetSymbolAddress((void**)&t0h,   g_t0h);
    cudaGetSymbolAddress((void**)&t1h,   g_t1h);
    cudaGetSymbolAddress((void**)&wup,   g_wup);
    cudaGetSymbolAddress((void**)&w2t,   g_w2t);
    cudaGetSymbolAddress((void**)&a2t,   g_a2t);
    cudaGetSymbolAddress((void**)&b2t,   g_b2t);
    cudaGetSymbolAddress((void**)&perm,  g_perm);
    cudaGetSymbolAddress((void**)&pos,   g_pos);
    cudaGetSymbolAddress((void**)&counts, g_counts);

    static cudaStream_t s2 = nullptr;
    static cudaEvent_t evFork = nullptr, evW = nullptr, evLn = nullptr, evSide = nullptr;
    if (s2 == nullptr) {
        cudaStreamCreateWithFlags(&s2, cudaStreamNonBlocking);
        cudaEventCreateWithFlags(&evFork, cudaEventDisableTiming);
        cudaEventCreateWithFlags(&evW,    cudaEventDisableTiming);
        cudaEventCreateWithFlags(&evLn,   cudaEventDisableTiming);
        cudaEventCreateWithFlags(&evSide, cudaEventDisableTiming);
    }

    // ---- fork side stream: all weight prep ----
    cudaEventRecord(evFork, 0);
    cudaStreamWaitEvent(s2, evFork, 0);
    transpose_w1<<<dim3(FFN / 32, HID / 32), 256, 0, s2>>>(W1, wup);
    prep_weights<<<dim3(32, 32, 5), 256, 0, s2>>>(a256_w1, a256_w2, a512_w1, a512_w2,
                                                  wup, a2t, b2t,
                                                  b1, a256_b1, a512_b1, bup);
    cudaEventRecord(evW, s2);      // wup/bup (and a2t/b2t in-stream) ready
    transpose_w2<<<dim3(HID / 32, FFN / 32), 256, 0, s2>>>(W2, ln_h_g, w2t);
    colsum_partial<<<dim3(HID / 128, 256), 128, 0, s2>>>(W2, ln_h_g, ln_h_b, p1, p2);
    colsum_reduce<<<HID / 256, 256, 0, s2>>>(p1, p2, b2, c1, c2);

    // ---- main chain: perm -> LN ----
    perm_kernel<<<1, 256>>>(widx, perm, pos, counts);
    ln1024_warp<<<TOKENS / 8, 256>>>(x, ln_in_g, ln_in_b, pos, xnh);
    cudaEventRecord(evLn, 0);

    // ---- side stream: adapter up + adapter down (overlaps with up_h) ----
    cudaStreamWaitEvent(s2, evLn, 0);
    gemm_up_adapt<<<dim3(6, TOKENS / 128), 256, GEMM_SMEM, s2>>>(
        xnh, wup, bup, counts, t0h, t1h);
    gemm_down<<<dim3(HID / 128, TOKENS / 128, 2), 256, GEMM_SMEM, s2>>>(
        t0h, a2t, a256_b2, ad0, t1h, b2t, a512_b2, ad1, counts);
    cudaEventRecord(evSide, s2);

    // ---- main chain: big up-projection (fused rowstat partials), reduce ----
    cudaStreamWaitEvent(0, evW, 0);
    gemm_up_h<<<dim3(FFN / 128, TOKENS / 128), 256, GEMM_SMEM>>>(xnh, wup, bup, hh, ps, pq);
    rowstat_reduce<<<TOKENS / 256, 256>>>(ps, pq, mu, inv);

    // ---- join, final ----
    cudaStreamWaitEvent(0, evSide, 0);
    gemm_final<<<dim3(HID / 128, TOKENS / 128), 256, GEMM_SMEM>>>(
        hh, w2t, c1, c2, mu, inv, wm, perm, counts, ad0, ad1, xnh, out);
}